// round 11
// baseline (speedup 1.0000x reference)
#include <cuda_runtime.h>
#include <cuda_bf16.h>
#include <cstdint>
#include <math.h>
#include <mma.h>

using namespace nvcuda;

#define NN 100000
#define EE 150000
#define DD 512
#define HH 8

#define GBM 128
#define GBN 128
#define GBK 32
#define APADE 8    // As row stride 40 bf16 = 80B = 5x16B (odd -> LDSM conflict-free)
#define BPADE 8    // Bs row stride 136 bf16 = 272B = 17x16B (odd -> LDSM conflict-free)

// ---------------- scratch ---------------------------------------------------
__device__ float g_h_o[(size_t)NN * DD];
__device__ float g_h_e[(size_t)NN * DD];
__device__ float g_out0[(size_t)NN * DD];
__device__ float g_out1[(size_t)NN * DD];
__device__ __nv_bfloat16 g_Ab[(size_t)NN * DD];   // bf16 A operand (reused 4x)
__device__ __nv_bfloat16 g_Wb[DD * DD];           // bf16 W operand (reused 3x)
__device__ float g_a_se[NN * HH];
__device__ float g_a_de[NN * HH];
__device__ float g_a_so[NN * HH];
__device__ float g_a_do[NN * HH];
__device__ unsigned g_amax[NN * HH];
__device__ float g_denom[NN * HH];
__device__ float g_ebuf[EE * HH];
__device__ float g_ksum[2 * DD];
__device__ float g_musum[2 * DD];

// ---------------- helpers ---------------------------------------------------
__device__ __forceinline__ unsigned mapf(float f) {
    unsigned u = __float_as_uint(f);
    return (u & 0x80000000u) ? ~u : (u | 0x80000000u);
}
__device__ __forceinline__ float unmapf(unsigned u) {
    return __uint_as_float((u & 0x80000000u) ? (u & 0x7FFFFFFFu) : ~u);
}

__global__ void zero_buf(float* p, long n) {
    long i = (long)blockIdx.x * blockDim.x + threadIdx.x;
    long stride = (long)gridDim.x * blockDim.x;
    for (; i < n; i += stride) p[i] = 0.0f;
}

__global__ void init_edge_state(unsigned* amax, float* denom, int n) {
    int i = blockIdx.x * blockDim.x + threadIdx.x;
    if (i < n) { amax[i] = 0x007FFFFFu; denom[i] = 0.0f; }  // mapf(-inf)
}

// ---------------- fp32 -> bf16 conversion (vectorized) ----------------------
__global__ void conv_bf(const float* __restrict__ src,
                        __nv_bfloat16* __restrict__ dst, long n) {
    long i = ((long)blockIdx.x * blockDim.x + threadIdx.x) * 4;
    long stride = (long)gridDim.x * blockDim.x * 4;
    for (; i < n; i += stride) {
        float4 v = *(const float4*)(src + i);
        *(__nv_bfloat162*)(dst + i)     = __floats2bfloat162_rn(v.x, v.y);
        *(__nv_bfloat162*)(dst + i + 2) = __floats2bfloat162_rn(v.z, v.w);
    }
}

// ---------------- fused relu + bf16 convert + column sums -------------------
__global__ void convmu(const float* __restrict__ outb,
                       __nv_bfloat16* __restrict__ dst,
                       float* __restrict__ musum, int M) {
    int f = threadIdx.x;                   // 512 threads = columns
    int chunk = (M + gridDim.x - 1) / gridDim.x;
    int r0 = blockIdx.x * chunk;
    int r1 = min(M, r0 + chunk);
    float acc = 0.f;
    for (int r = r0; r < r1; r++) {
        float v = fmaxf(outb[(size_t)r * DD + f], 0.f);
        acc += v;
        dst[(size_t)r * DD + f] = __float2bfloat16(v);
    }
    atomicAdd(&musum[f], acc);
}

// ---------------- BF16 TC GEMM, 2-stage cp.async, 1 sync/iter ---------------
// MODE 0: C = A@W + bias (stored fp32).
// MODE 1: epilogue accumulates sum_rows tanh(acc+bias) into ksum_out.
template <int MODE>
__global__ void __launch_bounds__(256) gemm_bf(
        const __nv_bfloat16* __restrict__ A, const __nv_bfloat16* __restrict__ W,
        const float* __restrict__ bias, float* __restrict__ C, int M,
        float* __restrict__ ksum_out) {
    __shared__ __nv_bfloat16 As[2][GBM][GBK + APADE];   // 2 x 128 x 40
    __shared__ __nv_bfloat16 Bs[2][GBK][GBN + BPADE];   // 2 x 32 x 136
    __shared__ float stage[8][16][20];
    __shared__ float ksred[GBN];

    int tid = threadIdx.x;
    int wid = tid >> 5;
    int lane = tid & 31;
    int warp_m = wid & 3;
    int warp_n = wid >> 2;
    int m0 = blockIdx.y * GBM;
    int n0 = blockIdx.x * GBN;
    int wm0 = warp_m * 32;
    int wn0 = warp_n * 64;

    if (MODE == 1 && tid < GBN) ksred[tid] = 0.0f;

    // A tile: 128x32 bf16 = 512 x 16B chunks; B tile: 32x128 bf16 = 512 chunks
    auto load_stage = [&](int s, int k0) {
#pragma unroll
        for (int it = 0; it < 2; it++) {
            int idx = tid + it * 256;
            int ar = idx >> 2, ac = (idx & 3) * 8;
            int gm = m0 + ar;
            const __nv_bfloat16* srcA =
                A + (size_t)(gm < M ? gm : M - 1) * DD + k0 + ac;
            uint32_t dstA = (uint32_t)__cvta_generic_to_shared(&As[s][ar][ac]);
            int szA = (gm < M) ? 16 : 0;
            asm volatile("cp.async.cg.shared.global [%0], [%1], 16, %2;"
                         :: "r"(dstA), "l"(srcA), "r"(szA));
            int br = idx >> 4, bc = (idx & 15) * 8;
            const __nv_bfloat16* srcB = W + (size_t)(k0 + br) * DD + n0 + bc;
            uint32_t dstB = (uint32_t)__cvta_generic_to_shared(&Bs[s][br][bc]);
            asm volatile("cp.async.cg.shared.global [%0], [%1], 16, 16;"
                         :: "r"(dstB), "l"(srcB));
        }
        asm volatile("cp.async.commit_group;");
    };

    wmma::fragment<wmma::accumulator, 16, 16, 16, float> acc[2][4];
#pragma unroll
    for (int i = 0; i < 2; i++)
#pragma unroll
        for (int j = 0; j < 4; j++) wmma::fill_fragment(acc[i][j], 0.0f);

    load_stage(0, 0);

    int sbuf = 0;
    for (int k0 = 0; k0 < DD; k0 += GBK) {
        // stage sbuf's data is in flight (committed); wait for it
        asm volatile("cp.async.wait_group 0;" ::: "memory");
        __syncthreads();
        // all warps finished computing from slot sbuf^1 (previous iter) —
        // safe to overwrite it with the next tile now, overlapping compute
        if (k0 + GBK < DD) load_stage(sbuf ^ 1, k0 + GBK);

#pragma unroll
        for (int kk = 0; kk < GBK; kk += 16) {
            wmma::fragment<wmma::matrix_a, 16, 16, 16, __nv_bfloat16,
                           wmma::row_major> af[2];
            wmma::fragment<wmma::matrix_b, 16, 16, 16, __nv_bfloat16,
                           wmma::row_major> bf[4];
#pragma unroll
            for (int i = 0; i < 2; i++)
                wmma::load_matrix_sync(af[i], &As[sbuf][wm0 + i * 16][kk],
                                       GBK + APADE);
#pragma unroll
            for (int j = 0; j < 4; j++)
                wmma::load_matrix_sync(bf[j], &Bs[sbuf][kk][wn0 + j * 16],
                                       GBN + BPADE);
#pragma unroll
            for (int i = 0; i < 2; i++)
#pragma unroll
                for (int j = 0; j < 4; j++)
                    wmma::mma_sync(acc[i][j], af[i], bf[j], acc[i][j]);
        }
        sbuf ^= 1;
    }
    __syncthreads();

    // ---------------- epilogue ----------------
    int r = lane >> 1;
    int cbase = (lane & 1) * 8;
#pragma unroll
    for (int i = 0; i < 2; i++) {
#pragma unroll
        for (int j = 0; j < 4; j++) {
            wmma::store_matrix_sync(&stage[wid][0][0], acc[i][j], 20,
                                    wmma::mem_row_major);
            __syncwarp();
            int grow = m0 + wm0 + i * 16 + r;
            int gcol = n0 + wn0 + j * 16 + cbase;
            if (grow < M) {
                float4 v1 = *(const float4*)(&stage[wid][r][cbase]);
                float4 v2 = *(const float4*)(&stage[wid][r][cbase + 4]);
                float4 b1 = *(const float4*)(bias + gcol);
                float4 b2 = *(const float4*)(bias + gcol + 4);
                v1.x += b1.x; v1.y += b1.y; v1.z += b1.z; v1.w += b1.w;
                v2.x += b2.x; v2.y += b2.y; v2.z += b2.z; v2.w += b2.w;
                if (MODE == 0) {
                    *(float4*)(C + (size_t)grow * DD + gcol) = v1;
                    *(float4*)(C + (size_t)grow * DD + gcol + 4) = v2;
                } else {
                    int lc = wn0 + j * 16 + cbase;
                    atomicAdd(&ksred[lc + 0], tanhf(v1.x));
                    atomicAdd(&ksred[lc + 1], tanhf(v1.y));
                    atomicAdd(&ksred[lc + 2], tanhf(v1.z));
                    atomicAdd(&ksred[lc + 3], tanhf(v1.w));
                    atomicAdd(&ksred[lc + 4], tanhf(v2.x));
                    atomicAdd(&ksred[lc + 5], tanhf(v2.y));
                    atomicAdd(&ksred[lc + 6], tanhf(v2.z));
                    atomicAdd(&ksred[lc + 7], tanhf(v2.w));
                }
            }
            __syncwarp();
        }
    }
    if (MODE == 1) {
        __syncthreads();
        if (tid < GBN) atomicAdd(&ksum_out[n0 + tid], ksred[tid]);
    }
}

// ---------------- attention dots: 1 read of h, up to 3 att pairs ------------
__global__ void compute_ah3(const float* __restrict__ hmat,
                            const float* __restrict__ att0, float* __restrict__ a0,
                            const float* __restrict__ att1, float* __restrict__ a1,
                            const float* __restrict__ att2, float* __restrict__ a2,
                            int n_nodes) {
    int gt = blockIdx.x * blockDim.x + threadIdx.x;
    int warp = gt >> 5;
    int lane = threadIdx.x & 31;
    if (warp >= n_nodes) return;
    int base = lane * 16;
    const float4* hp = (const float4*)(hmat + (size_t)warp * DD + base);
    const float4* ap0 = (const float4*)(att0 + base);
    const float4* ap1 = att1 ? (const float4*)(att1 + base) : nullptr;
    const float4* ap2 = att2 ? (const float4*)(att2 + base) : nullptr;
    float s0 = 0.f, s1 = 0.f, s2 = 0.f;
#pragma unroll
    for (int q = 0; q < 4; q++) {
        float4 hv = hp[q];
        float4 av = ap0[q];
        s0 += hv.x * av.x + hv.y * av.y + hv.z * av.z + hv.w * av.w;
        if (ap1) {
            float4 bv = ap1[q];
            s1 += hv.x * bv.x + hv.y * bv.y + hv.z * bv.z + hv.w * bv.w;
        }
        if (ap2) {
            float4 cv = ap2[q];
            s2 += hv.x * cv.x + hv.y * cv.y + hv.z * cv.z + hv.w * cv.w;
        }
    }
#pragma unroll
    for (int d = 1; d <= 2; d <<= 1) {
        s0 += __shfl_xor_sync(0xffffffffu, s0, d);
        s1 += __shfl_xor_sync(0xffffffffu, s1, d);
        s2 += __shfl_xor_sync(0xffffffffu, s2, d);
    }
    if ((lane & 3) == 0) {
        int o = warp * HH + (lane >> 2);
        a0[o] = s0;
        if (a1) a1[o] = s1;
        if (a2) a2[o] = s2;
    }
}

// ---------------- edge pass 1: alpha + segment max --------------------------
__global__ void edge_alpha_max(const int* __restrict__ src,
                               const int* __restrict__ dst,
                               const float* __restrict__ asrc,
                               const float* __restrict__ adst,
                               float* __restrict__ alpha,
                               unsigned* __restrict__ amax, int ne) {
    int i = blockIdx.x * blockDim.x + threadIdx.x;
    if (i >= ne * HH) return;
    int e = i >> 3, h = i & 7;
    float v = asrc[src[e] * HH + h] + adst[dst[e] * HH + h];
    v = (v > 0.f) ? v : 0.2f * v;
    alpha[i] = v;
    atomicMax(&amax[dst[e] * HH + h], mapf(v));
}

// ---------------- edge pass 2: exp + segment sum ----------------------------
__global__ void edge_exp_sum(const int* __restrict__ dst,
                             float* __restrict__ alpha,
                             const unsigned* __restrict__ amax,
                             float* __restrict__ denom, int ne) {
    int i = blockIdx.x * blockDim.x + threadIdx.x;
    if (i >= ne * HH) return;
    int e = i >> 3, h = i & 7;
    float ex = expf(alpha[i] - unmapf(amax[dst[e] * HH + h]));
    alpha[i] = ex;
    atomicAdd(&denom[dst[e] * HH + h], ex);
}

// ---------------- edge pass 3: weighted scatter (vector red) ----------------
__global__ void edge_scatter(const int* __restrict__ src,
                             const int* __restrict__ dst,
                             const float* __restrict__ hsrc,
                             const float* __restrict__ exbuf,
                             const float* __restrict__ denom,
                             float* __restrict__ outb, int ne) {
    int gt = blockIdx.x * blockDim.x + threadIdx.x;
    int e = gt >> 5;
    int lane = threadIdx.x & 31;
    if (e >= ne) return;
    int s = src[e], d = dst[e];
    int h = lane >> 2;
    float w = exbuf[e * HH + h] / (denom[d * HH + h] + 1e-16f);
    const float4* hp = (const float4*)(hsrc + (size_t)s * DD + lane * 16);
    float* op = outb + (size_t)d * DD + lane * 16;
#pragma unroll
    for (int q = 0; q < 4; q++) {
        float4 v = hp[q];
        asm volatile("red.global.add.v4.f32 [%0], {%1, %2, %3, %4};"
                     :: "l"(op + q * 4), "f"(v.x * w), "f"(v.y * w),
                        "f"(v.z * w), "f"(v.w * w)
                     : "memory");
    }
}

// ---------------- final semantic attention + pool + linear ------------------
__global__ void final_kernel(const float* __restrict__ qsem,
                             const float* __restrict__ linw,
                             const float* __restrict__ linb,
                             float* __restrict__ out) {
    __shared__ float sh[DD];
    __shared__ float sv[2];
    int f = threadIdx.x;
    const float invN = 1.0f / (float)NN;
    float q = qsem[f];
    float v0 = g_ksum[f] * invN * q;
    float v1 = g_ksum[DD + f] * invN * q;

    sh[f] = v0; __syncthreads();
    for (int s = 256; s > 0; s >>= 1) { if (f < s) sh[f] += sh[f + s]; __syncthreads(); }
    if (f == 0) sv[0] = sh[0];
    __syncthreads();
    sh[f] = v1; __syncthreads();
    for (int s = 256; s > 0; s >>= 1) { if (f < s) sh[f] += sh[f + s]; __syncthreads(); }
    if (f == 0) sv[1] = sh[0];
    __syncthreads();

    float s0 = sv[0], s1 = sv[1];
    float mx = fmaxf(s0, s1);
    float e0 = expf(s0 - mx), e1 = expf(s1 - mx);
    float sem0 = e0 / (e0 + e1), sem1 = e1 / (e0 + e1);

    float pooled = (sem0 * g_musum[f] + sem1 * g_musum[DD + f]) * invN;
    float w0 = pooled * linw[f * 2 + 0];
    float w1 = pooled * linw[f * 2 + 1];

    sh[f] = w0; __syncthreads();
    for (int s = 256; s > 0; s >>= 1) { if (f < s) sh[f] += sh[f + s]; __syncthreads(); }
    if (f == 0) out[0] = sh[0] + linb[0];
    __syncthreads();
    sh[f] = w1; __syncthreads();
    for (int s = 256; s > 0; s >>= 1) { if (f < s) sh[f] += sh[f + s]; __syncthreads(); }
    if (f == 0) out[1] = sh[0] + linb[1];
}

// ---------------- host launcher ---------------------------------------------
extern "C" void kernel_launch(void* const* d_in, const int* in_sizes, int n_in,
                              void* d_out, int out_size) {
    const float* x_o  = (const float*)d_in[0];
    const float* x_e  = (const float*)d_in[1];
    const int*   e2o  = (const int*)d_in[2];
    const int*   o2o  = (const int*)d_in[3];
    const float* powm = (const float*)d_in[4];
    const float* pob  = (const float*)d_in[5];
    const float* pewm = (const float*)d_in[6];
    const float* peb  = (const float*)d_in[7];
    const float* a_s_e2o = (const float*)d_in[8];
    const float* a_d_e2o = (const float*)d_in[9];
    const float* a_s_o2o = (const float*)d_in[10];
    const float* a_d_o2o = (const float*)d_in[11];
    const float* klw  = (const float*)d_in[12];
    const float* klb  = (const float*)d_in[13];
    const float* qsem = (const float*)d_in[14];
    const float* linw = (const float*)d_in[15];
    const float* linb = (const float*)d_in[16];
    float* out = (float*)d_out;

    void* p;
    float *h_o, *h_e, *out0, *out1, *a_se, *a_de, *a_so, *a_do, *denom, *ebuf, *ksum, *musum;
    __nv_bfloat16 *Ab, *Wb;
    unsigned* amax;
    cudaGetSymbolAddress(&p, g_h_o);  h_o  = (float*)p;
    cudaGetSymbolAddress(&p, g_h_e);  h_e  = (float*)p;
    cudaGetSymbolAddress(&p, g_out0); out0 = (float*)p;
    cudaGetSymbolAddress(&p, g_out1); out1 = (float*)p;
    cudaGetSymbolAddress(&p, g_Ab);   Ab   = (__nv_bfloat16*)p;
    cudaGetSymbolAddress(&p, g_Wb);   Wb   = (__nv_bfloat16*)p;
    cudaGetSymbolAddress(&p, g_a_se); a_se = (float*)p;
    cudaGetSymbolAddress(&p, g_a_de); a_de = (float*)p;
    cudaGetSymbolAddress(&p, g_a_so); a_so = (float*)p;
    cudaGetSymbolAddress(&p, g_a_do); a_do = (float*)p;
    cudaGetSymbolAddress(&p, g_amax); amax = (unsigned*)p;
    cudaGetSymbolAddress(&p, g_denom); denom = (float*)p;
    cudaGetSymbolAddress(&p, g_ebuf); ebuf = (float*)p;
    cudaGetSymbolAddress(&p, g_ksum); ksum = (float*)p;
    cudaGetSymbolAddress(&p, g_musum); musum = (float*)p;

    const long ND = (long)NN * DD;
    dim3 tcgrid(DD / GBN, (NN + GBM - 1) / GBM);   // (4, 782)

    // ---- GEMM 1 as launch #4 (ncu's capture point) ----
    conv_bf<<<256, 256>>>(powm, Wb, DD * DD);        // 1
    conv_bf<<<2048, 256>>>(x_o, Ab, ND);             // 2
    zero_buf<<<4, 256>>>(ksum, 2 * DD);              // 3
    gemm_bf<0><<<tcgrid, 256>>>(Ab, Wb, pob, h_o, NN, nullptr);   // 4 <- PROFILED

    zero_buf<<<4096, 256>>>(out0, ND);
    zero_buf<<<4096, 256>>>(out1, ND);
    zero_buf<<<4, 256>>>(musum, 2 * DD);

    // ---- GEMM 2: h_e = x_e @ proj_e_w + b ----
    conv_bf<<<256, 256>>>(pewm, Wb, DD * DD);
    conv_bf<<<2048, 256>>>(x_e, Ab, ND);
    gemm_bf<0><<<tcgrid, 256>>>(Ab, Wb, peb, h_e, NN, nullptr);

    int ah_blocks = (NN * 32 + 255) / 256;
    int eh_blocks = (EE * HH + 255) / 256;
    int sc_blocks = (EE * 32 + 255) / 256;
    int ie_blocks = (NN * HH + 255) / 256;

    // ---- attention dots ----
    compute_ah3<<<ah_blocks, 256>>>(h_o, a_d_e2o, a_de, a_s_o2o, a_so, a_d_o2o, a_do, NN);
    compute_ah3<<<ah_blocks, 256>>>(h_e, a_s_e2o, a_se, nullptr, nullptr, nullptr, nullptr, NN);

    // ---- metapath 0: entity -> openie ----
    init_edge_state<<<ie_blocks, 256>>>(amax, denom, NN * HH);
    edge_alpha_max<<<eh_blocks, 256>>>(e2o, e2o + EE, a_se, a_de, ebuf, amax, EE);
    edge_exp_sum<<<eh_blocks, 256>>>(e2o + EE, ebuf, amax, denom, EE);
    edge_scatter<<<sc_blocks, 256>>>(e2o, e2o + EE, h_e, ebuf, denom, out0, EE);

    // ---- metapath 1: openie -> openie ----
    init_edge_state<<<ie_blocks, 256>>>(amax, denom, NN * HH);
    edge_alpha_max<<<eh_blocks, 256>>>(o2o, o2o + EE, a_so, a_do, ebuf, amax, EE);
    edge_exp_sum<<<eh_blocks, 256>>>(o2o + EE, ebuf, amax, denom, EE);
    edge_scatter<<<sc_blocks, 256>>>(o2o, o2o + EE, h_o, ebuf, denom, out1, EE);

    // ---- semantic attention: ksum_m = sum_n tanh(relu(out_m) @ klw + b) ----
    conv_bf<<<256, 256>>>(klw, Wb, DD * DD);
    convmu<<<128, 512>>>(out0, Ab, musum, NN);
    gemm_bf<1><<<tcgrid, 256>>>(Ab, Wb, klb, nullptr, NN, ksum);
    convmu<<<128, 512>>>(out1, Ab, musum + DD, NN);
    gemm_bf<1><<<tcgrid, 256>>>(Ab, Wb, klb, nullptr, NN, ksum + DD);

    // ---- softmax over metapaths, pool, final linear ----
    final_kernel<<<1, 512>>>(qsem, linw, linb, out);
}

// round 12
// speedup vs baseline: 1.0338x; 1.0338x over previous
#include <cuda_runtime.h>
#include <cuda_bf16.h>
#include <cstdint>
#include <math.h>
#include <mma.h>

using namespace nvcuda;

#define NN 100000
#define EE 150000
#define DD 512
#define HH 8

#define GBM 128
#define GBN 128
#define GBK 32
#define APADE 8    // As row stride 40 bf16 = 5x16B (odd -> LDSM conflict-free)
#define BPADE 8    // Bs row stride 136 bf16 = 17x16B (odd -> LDSM conflict-free)

// ---------------- scratch ---------------------------------------------------
__device__ __nv_bfloat16 g_hb_o[(size_t)NN * DD];   // bf16 projected openie
__device__ __nv_bfloat16 g_hb_e[(size_t)NN * DD];   // bf16 projected entity
__device__ float g_out0[(size_t)NN * DD];
__device__ float g_out1[(size_t)NN * DD];
__device__ __nv_bfloat16 g_Ab[(size_t)NN * DD];     // bf16 A operand
__device__ __nv_bfloat16 g_Wb[DD * DD];             // bf16 W operand
__device__ float g_a_se[NN * HH];
__device__ float g_a_de[NN * HH];
__device__ float g_a_so[NN * HH];
__device__ float g_a_do[NN * HH];
__device__ unsigned g_amax[2 * NN * HH];
__device__ float g_denom[2 * NN * HH];
__device__ float g_ebuf[2 * EE * HH];
__device__ float g_ksum[2 * DD];
__device__ float g_musum[2 * DD];

// ---------------- helpers ---------------------------------------------------
__device__ __forceinline__ unsigned mapf(float f) {
    unsigned u = __float_as_uint(f);
    return (u & 0x80000000u) ? ~u : (u | 0x80000000u);
}
__device__ __forceinline__ float unmapf(unsigned u) {
    return __uint_as_float((u & 0x80000000u) ? (u & 0x7FFFFFFFu) : ~u);
}

__global__ void zero_buf(float* p, long n) {
    long i = (long)blockIdx.x * blockDim.x + threadIdx.x;
    long stride = (long)gridDim.x * blockDim.x;
    for (; i < n; i += stride) p[i] = 0.0f;
}

__global__ void init_edge_state(unsigned* amax, float* denom, int n) {
    int i = blockIdx.x * blockDim.x + threadIdx.x;
    if (i < n) { amax[i] = 0x007FFFFFu; denom[i] = 0.0f; }
}

// ---------------- fp32 -> bf16 conversion ------------------------------------
__global__ void conv_bf(const float* __restrict__ src,
                        __nv_bfloat16* __restrict__ dst, long n) {
    long i = ((long)blockIdx.x * blockDim.x + threadIdx.x) * 4;
    long stride = (long)gridDim.x * blockDim.x * 4;
    for (; i < n; i += stride) {
        float4 v = *(const float4*)(src + i);
        *(__nv_bfloat162*)(dst + i)     = __floats2bfloat162_rn(v.x, v.y);
        *(__nv_bfloat162*)(dst + i + 2) = __floats2bfloat162_rn(v.z, v.w);
    }
}

// ---------------- fused relu + bf16 convert + column sums --------------------
__global__ void convmu(const float* __restrict__ outb,
                       __nv_bfloat16* __restrict__ dst,
                       float* __restrict__ musum, int M) {
    int f = threadIdx.x;
    int chunk = (M + gridDim.x - 1) / gridDim.x;
    int r0 = blockIdx.x * chunk;
    int r1 = min(M, r0 + chunk);
    float acc = 0.f;
    for (int r = r0; r < r1; r++) {
        float v = fmaxf(outb[(size_t)r * DD + f], 0.f);
        acc += v;
        dst[(size_t)r * DD + f] = __float2bfloat16(v);
    }
    atomicAdd(&musum[f], acc);
}

// ---------------- BF16 TC GEMM, 2-stage cp.async -----------------------------
// MODE 0: C = bf16(A@W + bias) stored.
// MODE 1: epilogue accumulates sum_rows tanh(acc+bias) into ksum_out.
template <int MODE>
__global__ void __launch_bounds__(256) gemm_bf(
        const __nv_bfloat16* __restrict__ A, const __nv_bfloat16* __restrict__ W,
        const float* __restrict__ bias, void* __restrict__ Cv, int M,
        float* __restrict__ ksum_out) {
    __shared__ __nv_bfloat16 As[2][GBM][GBK + APADE];
    __shared__ __nv_bfloat16 Bs[2][GBK][GBN + BPADE];
    __shared__ float stage[8][16][20];
    __shared__ float ksred[GBN];

    int tid = threadIdx.x;
    int wid = tid >> 5;
    int lane = tid & 31;
    int warp_m = wid & 3;
    int warp_n = wid >> 2;
    int m0 = blockIdx.y * GBM;
    int n0 = blockIdx.x * GBN;
    int wm0 = warp_m * 32;
    int wn0 = warp_n * 64;

    if (MODE == 1 && tid < GBN) ksred[tid] = 0.0f;

    auto load_stage = [&](int s, int k0) {
#pragma unroll
        for (int it = 0; it < 2; it++) {
            int idx = tid + it * 256;
            int ar = idx >> 2, ac = (idx & 3) * 8;
            int gm = m0 + ar;
            const __nv_bfloat16* srcA =
                A + (size_t)(gm < M ? gm : M - 1) * DD + k0 + ac;
            uint32_t dstA = (uint32_t)__cvta_generic_to_shared(&As[s][ar][ac]);
            int szA = (gm < M) ? 16 : 0;
            asm volatile("cp.async.cg.shared.global [%0], [%1], 16, %2;"
                         :: "r"(dstA), "l"(srcA), "r"(szA));
            int br = idx >> 4, bc = (idx & 15) * 8;
            const __nv_bfloat16* srcB = W + (size_t)(k0 + br) * DD + n0 + bc;
            uint32_t dstB = (uint32_t)__cvta_generic_to_shared(&Bs[s][br][bc]);
            asm volatile("cp.async.cg.shared.global [%0], [%1], 16, 16;"
                         :: "r"(dstB), "l"(srcB));
        }
        asm volatile("cp.async.commit_group;");
    };

    wmma::fragment<wmma::accumulator, 16, 16, 16, float> acc[2][4];
#pragma unroll
    for (int i = 0; i < 2; i++)
#pragma unroll
        for (int j = 0; j < 4; j++) wmma::fill_fragment(acc[i][j], 0.0f);

    load_stage(0, 0);

    int sbuf = 0;
    for (int k0 = 0; k0 < DD; k0 += GBK) {
        asm volatile("cp.async.wait_group 0;" ::: "memory");
        __syncthreads();
        if (k0 + GBK < DD) load_stage(sbuf ^ 1, k0 + GBK);

#pragma unroll
        for (int kk = 0; kk < GBK; kk += 16) {
            wmma::fragment<wmma::matrix_a, 16, 16, 16, __nv_bfloat16,
                           wmma::row_major> af[2];
            wmma::fragment<wmma::matrix_b, 16, 16, 16, __nv_bfloat16,
                           wmma::row_major> bf[4];
#pragma unroll
            for (int i = 0; i < 2; i++)
                wmma::load_matrix_sync(af[i], &As[sbuf][wm0 + i * 16][kk],
                                       GBK + APADE);
#pragma unroll
            for (int j = 0; j < 4; j++)
                wmma::load_matrix_sync(bf[j], &Bs[sbuf][kk][wn0 + j * 16],
                                       GBN + BPADE);
#pragma unroll
            for (int i = 0; i < 2; i++)
#pragma unroll
                for (int j = 0; j < 4; j++)
                    wmma::mma_sync(acc[i][j], af[i], bf[j], acc[i][j]);
        }
        sbuf ^= 1;
    }
    __syncthreads();

    // ---------------- epilogue ----------------
    int r = lane >> 1;
    int cbase = (lane & 1) * 8;
#pragma unroll
    for (int i = 0; i < 2; i++) {
#pragma unroll
        for (int j = 0; j < 4; j++) {
            wmma::store_matrix_sync(&stage[wid][0][0], acc[i][j], 20,
                                    wmma::mem_row_major);
            __syncwarp();
            int grow = m0 + wm0 + i * 16 + r;
            int gcol = n0 + wn0 + j * 16 + cbase;
            if (grow < M) {
                float4 v1 = *(const float4*)(&stage[wid][r][cbase]);
                float4 v2 = *(const float4*)(&stage[wid][r][cbase + 4]);
                float4 b1 = *(const float4*)(bias + gcol);
                float4 b2 = *(const float4*)(bias + gcol + 4);
                v1.x += b1.x; v1.y += b1.y; v1.z += b1.z; v1.w += b1.w;
                v2.x += b2.x; v2.y += b2.y; v2.z += b2.z; v2.w += b2.w;
                if (MODE == 0) {
                    __nv_bfloat162 r0 = __floats2bfloat162_rn(v1.x, v1.y);
                    __nv_bfloat162 r1 = __floats2bfloat162_rn(v1.z, v1.w);
                    __nv_bfloat162 r2 = __floats2bfloat162_rn(v2.x, v2.y);
                    __nv_bfloat162 r3 = __floats2bfloat162_rn(v2.z, v2.w);
                    uint4 ov;
                    ov.x = *reinterpret_cast<unsigned*>(&r0);
                    ov.y = *reinterpret_cast<unsigned*>(&r1);
                    ov.z = *reinterpret_cast<unsigned*>(&r2);
                    ov.w = *reinterpret_cast<unsigned*>(&r3);
                    *(uint4*)((__nv_bfloat16*)Cv + (size_t)grow * DD + gcol) = ov;
                } else {
                    int lc = wn0 + j * 16 + cbase;
                    atomicAdd(&ksred[lc + 0], tanhf(v1.x));
                    atomicAdd(&ksred[lc + 1], tanhf(v1.y));
                    atomicAdd(&ksred[lc + 2], tanhf(v1.z));
                    atomicAdd(&ksred[lc + 3], tanhf(v1.w));
                    atomicAdd(&ksred[lc + 4], tanhf(v2.x));
                    atomicAdd(&ksred[lc + 5], tanhf(v2.y));
                    atomicAdd(&ksred[lc + 6], tanhf(v2.z));
                    atomicAdd(&ksred[lc + 7], tanhf(v2.w));
                }
            }
            __syncwarp();
        }
    }
    if (MODE == 1) {
        __syncthreads();
        if (tid < GBN) atomicAdd(&ksum_out[n0 + tid], ksred[tid]);
    }
}

// ---------------- attention dots from bf16 h --------------------------------
__global__ void compute_ah3(const __nv_bfloat16* __restrict__ hmat,
                            const float* __restrict__ att0, float* __restrict__ a0,
                            const float* __restrict__ att1, float* __restrict__ a1,
                            const float* __restrict__ att2, float* __restrict__ a2,
                            int n_nodes) {
    int gt = blockIdx.x * blockDim.x + threadIdx.x;
    int warp = gt >> 5;
    int lane = threadIdx.x & 31;
    if (warp >= n_nodes) return;
    int base = lane * 16;                 // head = lane>>2 (64 elems/head)
    const uint4* hp = (const uint4*)(hmat + (size_t)warp * DD + base);
    uint4 qa = hp[0], qb = hp[1];
    __nv_bfloat162* pa = reinterpret_cast<__nv_bfloat162*>(&qa);
    __nv_bfloat162* pb = reinterpret_cast<__nv_bfloat162*>(&qb);
    float hv[16];
#pragma unroll
    for (int j = 0; j < 4; j++) {
        float2 f = __bfloat1622float2(pa[j]);
        hv[2 * j] = f.x; hv[2 * j + 1] = f.y;
        float2 g = __bfloat1622float2(pb[j]);
        hv[8 + 2 * j] = g.x; hv[8 + 2 * j + 1] = g.y;
    }
    float s0 = 0.f, s1 = 0.f, s2 = 0.f;
    const float4* ap0 = (const float4*)(att0 + base);
    const float4* ap1 = att1 ? (const float4*)(att1 + base) : nullptr;
    const float4* ap2 = att2 ? (const float4*)(att2 + base) : nullptr;
#pragma unroll
    for (int q = 0; q < 4; q++) {
        float4 av = ap0[q];
        s0 += hv[q*4]*av.x + hv[q*4+1]*av.y + hv[q*4+2]*av.z + hv[q*4+3]*av.w;
        if (ap1) {
            float4 bv = ap1[q];
            s1 += hv[q*4]*bv.x + hv[q*4+1]*bv.y + hv[q*4+2]*bv.z + hv[q*4+3]*bv.w;
        }
        if (ap2) {
            float4 cv = ap2[q];
            s2 += hv[q*4]*cv.x + hv[q*4+1]*cv.y + hv[q*4+2]*cv.z + hv[q*4+3]*cv.w;
        }
    }
#pragma unroll
    for (int d = 1; d <= 2; d <<= 1) {
        s0 += __shfl_xor_sync(0xffffffffu, s0, d);
        s1 += __shfl_xor_sync(0xffffffffu, s1, d);
        s2 += __shfl_xor_sync(0xffffffffu, s2, d);
    }
    if ((lane & 3) == 0) {
        int o = warp * HH + (lane >> 2);
        a0[o] = s0;
        if (a1) a1[o] = s1;
        if (a2) a2[o] = s2;
    }
}

// ---------------- merged edge pass 1: alpha + segment max -------------------
__global__ void edge_alpha_max2(
        const int* __restrict__ s0p, const int* __restrict__ d0p,
        const int* __restrict__ s1p, const int* __restrict__ d1p,
        const float* __restrict__ ase, const float* __restrict__ ade,
        const float* __restrict__ aso, const float* __restrict__ ado,
        float* __restrict__ alpha, unsigned* __restrict__ amax, int ne) {
    int i = blockIdx.x * blockDim.x + threadIdx.x;
    int half = ne * HH;
    if (i >= 2 * half) return;
    int m = i >= half;
    int li = m ? i - half : i;
    int e = li >> 3, h = li & 7;
    const int* sp = m ? s1p : s0p;
    const int* dp = m ? d1p : d0p;
    const float* as = m ? aso : ase;
    const float* ad = m ? ado : ade;
    float v = as[sp[e] * HH + h] + ad[dp[e] * HH + h];
    v = (v > 0.f) ? v : 0.2f * v;
    alpha[i] = v;
    atomicMax(&amax[m * NN * HH + dp[e] * HH + h], mapf(v));
}

// ---------------- merged edge pass 2: exp + segment sum ---------------------
__global__ void edge_exp_sum2(
        const int* __restrict__ d0p, const int* __restrict__ d1p,
        float* __restrict__ alpha, const unsigned* __restrict__ amax,
        float* __restrict__ denom, int ne) {
    int i = blockIdx.x * blockDim.x + threadIdx.x;
    int half = ne * HH;
    if (i >= 2 * half) return;
    int m = i >= half;
    int li = m ? i - half : i;
    int e = li >> 3, h = li & 7;
    const int* dp = m ? d1p : d0p;
    int off = m * NN * HH + dp[e] * HH + h;
    float ex = expf(alpha[i] - unmapf(amax[off]));
    alpha[i] = ex;
    atomicAdd(&denom[off], ex);
}

// ---------------- merged edge pass 3: weighted scatter ----------------------
__global__ void edge_scatter2(
        const int* __restrict__ s0p, const int* __restrict__ d0p,
        const int* __restrict__ s1p, const int* __restrict__ d1p,
        const __nv_bfloat16* __restrict__ h0,   // metapath 0 source = h_e
        const __nv_bfloat16* __restrict__ h1,   // metapath 1 source = h_o
        const float* __restrict__ exbuf, const float* __restrict__ denom,
        float* __restrict__ out0, float* __restrict__ out1, int ne) {
    int gt = blockIdx.x * blockDim.x + threadIdx.x;
    int e = gt >> 5;
    int lane = threadIdx.x & 31;
    if (e >= 2 * ne) return;
    int m = e >= ne;
    int le = m ? e - ne : e;
    int s = m ? s1p[le] : s0p[le];
    int d = m ? d1p[le] : d0p[le];
    const __nv_bfloat16* hsrc = m ? h1 : h0;
    float* outb = m ? out1 : out0;
    int h = lane >> 2;
    float w = exbuf[e * HH + h] / (denom[m * NN * HH + d * HH + h] + 1e-16f);
    const uint4* hp = (const uint4*)(hsrc + (size_t)s * DD + lane * 16);
    uint4 qa = hp[0], qb = hp[1];
    __nv_bfloat162* pa = reinterpret_cast<__nv_bfloat162*>(&qa);
    __nv_bfloat162* pb = reinterpret_cast<__nv_bfloat162*>(&qb);
    float v[16];
#pragma unroll
    for (int j = 0; j < 4; j++) {
        float2 f = __bfloat1622float2(pa[j]);
        v[2 * j] = f.x; v[2 * j + 1] = f.y;
        float2 g = __bfloat1622float2(pb[j]);
        v[8 + 2 * j] = g.x; v[8 + 2 * j + 1] = g.y;
    }
    float* op = outb + (size_t)d * DD + lane * 16;
#pragma unroll
    for (int q = 0; q < 4; q++) {
        asm volatile("red.global.add.v4.f32 [%0], {%1, %2, %3, %4};"
                     :: "l"(op + q * 4), "f"(v[q*4] * w), "f"(v[q*4+1] * w),
                        "f"(v[q*4+2] * w), "f"(v[q*4+3] * w)
                     : "memory");
    }
}

// ---------------- final semantic attention + pool + linear ------------------
__global__ void final_kernel(const float* __restrict__ qsem,
                             const float* __restrict__ linw,
                             const float* __restrict__ linb,
                             float* __restrict__ out) {
    __shared__ float sh[DD];
    __shared__ float sv[2];
    int f = threadIdx.x;
    const float invN = 1.0f / (float)NN;
    float q = qsem[f];
    float v0 = g_ksum[f] * invN * q;
    float v1 = g_ksum[DD + f] * invN * q;

    sh[f] = v0; __syncthreads();
    for (int s = 256; s > 0; s >>= 1) { if (f < s) sh[f] += sh[f + s]; __syncthreads(); }
    if (f == 0) sv[0] = sh[0];
    __syncthreads();
    sh[f] = v1; __syncthreads();
    for (int s = 256; s > 0; s >>= 1) { if (f < s) sh[f] += sh[f + s]; __syncthreads(); }
    if (f == 0) sv[1] = sh[0];
    __syncthreads();

    float s0 = sv[0], s1 = sv[1];
    float mx = fmaxf(s0, s1);
    float e0 = expf(s0 - mx), e1 = expf(s1 - mx);
    float sem0 = e0 / (e0 + e1), sem1 = e1 / (e0 + e1);

    float pooled = (sem0 * g_musum[f] + sem1 * g_musum[DD + f]) * invN;
    float w0 = pooled * linw[f * 2 + 0];
    float w1 = pooled * linw[f * 2 + 1];

    sh[f] = w0; __syncthreads();
    for (int s = 256; s > 0; s >>= 1) { if (f < s) sh[f] += sh[f + s]; __syncthreads(); }
    if (f == 0) out[0] = sh[0] + linb[0];
    __syncthreads();
    sh[f] = w1; __syncthreads();
    for (int s = 256; s > 0; s >>= 1) { if (f < s) sh[f] += sh[f + s]; __syncthreads(); }
    if (f == 0) out[1] = sh[0] + linb[1];
}

// ---------------- host launcher ---------------------------------------------
extern "C" void kernel_launch(void* const* d_in, const int* in_sizes, int n_in,
                              void* d_out, int out_size) {
    const float* x_o  = (const float*)d_in[0];
    const float* x_e  = (const float*)d_in[1];
    const int*   e2o  = (const int*)d_in[2];
    const int*   o2o  = (const int*)d_in[3];
    const float* powm = (const float*)d_in[4];
    const float* pob  = (const float*)d_in[5];
    const float* pewm = (const float*)d_in[6];
    const float* peb  = (const float*)d_in[7];
    const float* a_s_e2o = (const float*)d_in[8];
    const float* a_d_e2o = (const float*)d_in[9];
    const float* a_s_o2o = (const float*)d_in[10];
    const float* a_d_o2o = (const float*)d_in[11];
    const float* klw  = (const float*)d_in[12];
    const float* klb  = (const float*)d_in[13];
    const float* qsem = (const float*)d_in[14];
    const float* linw = (const float*)d_in[15];
    const float* linb = (const float*)d_in[16];
    float* out = (float*)d_out;

    void* p;
    float *out0, *out1, *a_se, *a_de, *a_so, *a_do, *denom, *ebuf, *ksum, *musum;
    __nv_bfloat16 *hb_o, *hb_e, *Ab, *Wb;
    unsigned* amax;
    cudaGetSymbolAddress(&p, g_hb_o); hb_o = (__nv_bfloat16*)p;
    cudaGetSymbolAddress(&p, g_hb_e); hb_e = (__nv_bfloat16*)p;
    cudaGetSymbolAddress(&p, g_out0); out0 = (float*)p;
    cudaGetSymbolAddress(&p, g_out1); out1 = (float*)p;
    cudaGetSymbolAddress(&p, g_Ab);   Ab   = (__nv_bfloat16*)p;
    cudaGetSymbolAddress(&p, g_Wb);   Wb   = (__nv_bfloat16*)p;
    cudaGetSymbolAddress(&p, g_a_se); a_se = (float*)p;
    cudaGetSymbolAddress(&p, g_a_de); a_de = (float*)p;
    cudaGetSymbolAddress(&p, g_a_so); a_so = (float*)p;
    cudaGetSymbolAddress(&p, g_a_do); a_do = (float*)p;
    cudaGetSymbolAddress(&p, g_amax); amax = (unsigned*)p;
    cudaGetSymbolAddress(&p, g_denom); denom = (float*)p;
    cudaGetSymbolAddress(&p, g_ebuf); ebuf = (float*)p;
    cudaGetSymbolAddress(&p, g_ksum); ksum = (float*)p;
    cudaGetSymbolAddress(&p, g_musum); musum = (float*)p;

    const long ND = (long)NN * DD;
    dim3 tcgrid(DD / GBN, (NN + GBM - 1) / GBM);   // (4, 782)

    // ---- GEMM 1 as launch #4 (ncu's capture point) ----
    conv_bf<<<256, 256>>>(powm, Wb, DD * DD);        // 1
    conv_bf<<<2048, 256>>>(x_o, Ab, ND);             // 2
    zero_buf<<<4, 256>>>(ksum, 2 * DD);              // 3
    gemm_bf<0><<<tcgrid, 256>>>(Ab, Wb, pob, hb_o, NN, nullptr);  // 4 PROFILED

    zero_buf<<<4096, 256>>>(out0, ND);
    zero_buf<<<4096, 256>>>(out1, ND);
    zero_buf<<<4, 256>>>(musum, 2 * DD);

    // ---- GEMM 2: hb_e = bf16(x_e @ proj_e_w + b) ----
    conv_bf<<<256, 256>>>(pewm, Wb, DD * DD);
    conv_bf<<<2048, 256>>>(x_e, Ab, ND);
    gemm_bf<0><<<tcgrid, 256>>>(Ab, Wb, peb, hb_e, NN, nullptr);

    int ah_blocks = (NN * 32 + 255) / 256;
    int e2_blocks = (2 * EE * HH + 255) / 256;
    int sc2_blocks = (2 * EE * 32 + 255) / 256;
    int ie_blocks = (2 * NN * HH + 255) / 256;

    // ---- attention dots ----
    compute_ah3<<<ah_blocks, 256>>>(hb_o, a_d_e2o, a_de, a_s_o2o, a_so, a_d_o2o, a_do, NN);
    compute_ah3<<<ah_blocks, 256>>>(hb_e, a_s_e2o, a_se, nullptr, nullptr, nullptr, nullptr, NN);

    // ---- merged edge passes (both metapaths per launch) ----
    init_edge_state<<<ie_blocks, 256>>>(amax, denom, 2 * NN * HH);
    edge_alpha_max2<<<e2_blocks, 256>>>(e2o, e2o + EE, o2o, o2o + EE,
                                        a_se, a_de, a_so, a_do, ebuf, amax, EE);
    edge_exp_sum2<<<e2_blocks, 256>>>(e2o + EE, o2o + EE, ebuf, amax, denom, EE);
    edge_scatter2<<<sc2_blocks, 256>>>(e2o, e2o + EE, o2o, o2o + EE,
                                       hb_e, hb_o, ebuf, denom, out0, out1, EE);

    // ---- semantic attention: ksum_m = sum_n tanh(relu(out_m) @ klw + b) ----
    conv_bf<<<256, 256>>>(klw, Wb, DD * DD);
    convmu<<<128, 512>>>(out0, Ab, musum, NN);
    gemm_bf<1><<<tcgrid, 256>>>(Ab, Wb, klb, nullptr, NN, ksum);
    convmu<<<128, 512>>>(out1, Ab, musum + DD, NN);
    gemm_bf<1><<<tcgrid, 256>>>(Ab, Wb, klb, nullptr, NN, ksum + DD);

    // ---- softmax over metapaths, pool, final linear ----
    final_kernel<<<1, 512>>>(qsem, linw, linb, out);
}

// round 13
// speedup vs baseline: 1.1662x; 1.1281x over previous
#include <cuda_runtime.h>
#include <cuda_bf16.h>
#include <cstdint>
#include <math.h>
#include <mma.h>

using namespace nvcuda;

#define NN 100000
#define EE 150000
#define DD 512
#define HH 8

#define GBM 128
#define GBN 128
#define GBK 32
#define APADE 8
#define BPADE 8

// ---------------- scratch ---------------------------------------------------
__device__ __nv_bfloat16 g_hb_o[(size_t)NN * DD];
__device__ __nv_bfloat16 g_hb_e[(size_t)NN * DD];
__device__ __nv_bfloat16 g_Ab[(size_t)NN * DD];
__device__ __nv_bfloat16 g_A0[(size_t)NN * DD];     // gathered metapath 0 (bf16, relu'd)
__device__ __nv_bfloat16 g_A1[(size_t)NN * DD];     // gathered metapath 1
__device__ __nv_bfloat16 g_Wb[DD * DD];
__device__ float g_a_se[NN * HH];
__device__ float g_a_de[NN * HH];
__device__ float g_a_so[NN * HH];
__device__ float g_a_do[NN * HH];
__device__ unsigned g_amax[2 * NN * HH];
__device__ float g_denom[2 * NN * HH];
__device__ float g_ebuf[2 * EE * HH];
__device__ int g_deg[2 * NN];
__device__ int g_cur[2 * NN];
__device__ int g_startArr[2 * NN];
__device__ int g_bsum[256];
__device__ int g_eidx[2 * EE];
__device__ int g_esrc[2 * EE];
__device__ float g_ksum[2 * DD];
__device__ float g_musum[2 * DD];

// ---------------- helpers ---------------------------------------------------
__device__ __forceinline__ unsigned mapf(float f) {
    unsigned u = __float_as_uint(f);
    return (u & 0x80000000u) ? ~u : (u | 0x80000000u);
}
__device__ __forceinline__ float unmapf(unsigned u) {
    return __uint_as_float((u & 0x80000000u) ? (u & 0x7FFFFFFFu) : ~u);
}

__global__ void zero_buf(float* p, long n) {
    long i = (long)blockIdx.x * blockDim.x + threadIdx.x;
    long stride = (long)gridDim.x * blockDim.x;
    for (; i < n; i += stride) p[i] = 0.0f;
}

// init amax/denom (2*NN*HH) and deg/cur (2*NN)
__global__ void init_edge_state2(unsigned* amax, float* denom, int* deg,
                                 int* cur, int n) {
    int i = blockIdx.x * blockDim.x + threadIdx.x;
    if (i < n) { amax[i] = 0x007FFFFFu; denom[i] = 0.0f; }
    if (i < 2 * NN) { deg[i] = 0; cur[i] = 0; }
}

// ---------------- fp32 -> bf16 ----------------------------------------------
__global__ void conv_bf(const float* __restrict__ src,
                        __nv_bfloat16* __restrict__ dst, long n) {
    long i = ((long)blockIdx.x * blockDim.x + threadIdx.x) * 4;
    long stride = (long)gridDim.x * blockDim.x * 4;
    for (; i < n; i += stride) {
        float4 v = *(const float4*)(src + i);
        *(__nv_bfloat162*)(dst + i)     = __floats2bfloat162_rn(v.x, v.y);
        *(__nv_bfloat162*)(dst + i + 2) = __floats2bfloat162_rn(v.z, v.w);
    }
}

// ---------------- column sums of bf16 matrix --------------------------------
__global__ void mu_bf(const __nv_bfloat16* __restrict__ a,
                      float* __restrict__ musum, int M) {
    int f = threadIdx.x;
    int chunk = (M + gridDim.x - 1) / gridDim.x;
    int r0 = blockIdx.x * chunk;
    int r1 = min(M, r0 + chunk);
    float acc = 0.f;
    for (int r = r0; r < r1; r++)
        acc += __bfloat162float(a[(size_t)r * DD + f]);
    atomicAdd(&musum[f], acc);
}

// ---------------- BF16 TC GEMM, 2-stage cp.async -----------------------------
// MODE 0: C = bf16(A@W + bias) stored.
// MODE 1: epilogue accumulates sum_rows tanh(acc+bias) into ksum_out.
template <int MODE>
__global__ void __launch_bounds__(256) gemm_bf(
        const __nv_bfloat16* __restrict__ A, const __nv_bfloat16* __restrict__ W,
        const float* __restrict__ bias, void* __restrict__ Cv, int M,
        float* __restrict__ ksum_out) {
    __shared__ __nv_bfloat16 As[2][GBM][GBK + APADE];
    __shared__ __nv_bfloat16 Bs[2][GBK][GBN + BPADE];
    __shared__ float stage[8][16][20];
    __shared__ float ksred[GBN];

    int tid = threadIdx.x;
    int wid = tid >> 5;
    int lane = tid & 31;
    int warp_m = wid & 3;
    int warp_n = wid >> 2;
    int m0 = blockIdx.y * GBM;
    int n0 = blockIdx.x * GBN;
    int wm0 = warp_m * 32;
    int wn0 = warp_n * 64;

    if (MODE == 1 && tid < GBN) ksred[tid] = 0.0f;

    auto load_stage = [&](int s, int k0) {
#pragma unroll
        for (int it = 0; it < 2; it++) {
            int idx = tid + it * 256;
            int ar = idx >> 2, ac = (idx & 3) * 8;
            int gm = m0 + ar;
            const __nv_bfloat16* srcA =
                A + (size_t)(gm < M ? gm : M - 1) * DD + k0 + ac;
            uint32_t dstA = (uint32_t)__cvta_generic_to_shared(&As[s][ar][ac]);
            int szA = (gm < M) ? 16 : 0;
            asm volatile("cp.async.cg.shared.global [%0], [%1], 16, %2;"
                         :: "r"(dstA), "l"(srcA), "r"(szA));
            int br = idx >> 4, bc = (idx & 15) * 8;
            const __nv_bfloat16* srcB = W + (size_t)(k0 + br) * DD + n0 + bc;
            uint32_t dstB = (uint32_t)__cvta_generic_to_shared(&Bs[s][br][bc]);
            asm volatile("cp.async.cg.shared.global [%0], [%1], 16, 16;"
                         :: "r"(dstB), "l"(srcB));
        }
        asm volatile("cp.async.commit_group;");
    };

    wmma::fragment<wmma::accumulator, 16, 16, 16, float> acc[2][4];
#pragma unroll
    for (int i = 0; i < 2; i++)
#pragma unroll
        for (int j = 0; j < 4; j++) wmma::fill_fragment(acc[i][j], 0.0f);

    load_stage(0, 0);

    int sbuf = 0;
    for (int k0 = 0; k0 < DD; k0 += GBK) {
        asm volatile("cp.async.wait_group 0;" ::: "memory");
        __syncthreads();
        if (k0 + GBK < DD) load_stage(sbuf ^ 1, k0 + GBK);

#pragma unroll
        for (int kk = 0; kk < GBK; kk += 16) {
            wmma::fragment<wmma::matrix_a, 16, 16, 16, __nv_bfloat16,
                           wmma::row_major> af[2];
            wmma::fragment<wmma::matrix_b, 16, 16, 16, __nv_bfloat16,
                           wmma::row_major> bf[4];
#pragma unroll
            for (int i = 0; i < 2; i++)
                wmma::load_matrix_sync(af[i], &As[sbuf][wm0 + i * 16][kk],
                                       GBK + APADE);
#pragma unroll
            for (int j = 0; j < 4; j++)
                wmma::load_matrix_sync(bf[j], &Bs[sbuf][kk][wn0 + j * 16],
                                       GBN + BPADE);
#pragma unroll
            for (int i = 0; i < 2; i++)
#pragma unroll
                for (int j = 0; j < 4; j++)
                    wmma::mma_sync(acc[i][j], af[i], bf[j], acc[i][j]);
        }
        sbuf ^= 1;
    }
    __syncthreads();

    int r = lane >> 1;
    int cbase = (lane & 1) * 8;
#pragma unroll
    for (int i = 0; i < 2; i++) {
#pragma unroll
        for (int j = 0; j < 4; j++) {
            wmma::store_matrix_sync(&stage[wid][0][0], acc[i][j], 20,
                                    wmma::mem_row_major);
            __syncwarp();
            int grow = m0 + wm0 + i * 16 + r;
            int gcol = n0 + wn0 + j * 16 + cbase;
            if (grow < M) {
                float4 v1 = *(const float4*)(&stage[wid][r][cbase]);
                float4 v2 = *(const float4*)(&stage[wid][r][cbase + 4]);
                float4 b1 = *(const float4*)(bias + gcol);
                float4 b2 = *(const float4*)(bias + gcol + 4);
                v1.x += b1.x; v1.y += b1.y; v1.z += b1.z; v1.w += b1.w;
                v2.x += b2.x; v2.y += b2.y; v2.z += b2.z; v2.w += b2.w;
                if (MODE == 0) {
                    __nv_bfloat162 r0 = __floats2bfloat162_rn(v1.x, v1.y);
                    __nv_bfloat162 r1 = __floats2bfloat162_rn(v1.z, v1.w);
                    __nv_bfloat162 r2 = __floats2bfloat162_rn(v2.x, v2.y);
                    __nv_bfloat162 r3 = __floats2bfloat162_rn(v2.z, v2.w);
                    uint4 ov;
                    ov.x = *reinterpret_cast<unsigned*>(&r0);
                    ov.y = *reinterpret_cast<unsigned*>(&r1);
                    ov.z = *reinterpret_cast<unsigned*>(&r2);
                    ov.w = *reinterpret_cast<unsigned*>(&r3);
                    *(uint4*)((__nv_bfloat16*)Cv + (size_t)grow * DD + gcol) = ov;
                } else {
                    int lc = wn0 + j * 16 + cbase;
                    atomicAdd(&ksred[lc + 0], tanhf(v1.x));
                    atomicAdd(&ksred[lc + 1], tanhf(v1.y));
                    atomicAdd(&ksred[lc + 2], tanhf(v1.z));
                    atomicAdd(&ksred[lc + 3], tanhf(v1.w));
                    atomicAdd(&ksred[lc + 4], tanhf(v2.x));
                    atomicAdd(&ksred[lc + 5], tanhf(v2.y));
                    atomicAdd(&ksred[lc + 6], tanhf(v2.z));
                    atomicAdd(&ksred[lc + 7], tanhf(v2.w));
                }
            }
            __syncwarp();
        }
    }
    if (MODE == 1) {
        __syncthreads();
        if (tid < GBN) atomicAdd(&ksum_out[n0 + tid], ksred[tid]);
    }
}

// ---------------- attention dots from bf16 h --------------------------------
__global__ void compute_ah3(const __nv_bfloat16* __restrict__ hmat,
                            const float* __restrict__ att0, float* __restrict__ a0,
                            const float* __restrict__ att1, float* __restrict__ a1,
                            const float* __restrict__ att2, float* __restrict__ a2,
                            int n_nodes) {
    int gt = blockIdx.x * blockDim.x + threadIdx.x;
    int warp = gt >> 5;
    int lane = threadIdx.x & 31;
    if (warp >= n_nodes) return;
    int base = lane * 16;
    const uint4* hp = (const uint4*)(hmat + (size_t)warp * DD + base);
    uint4 qa = hp[0], qb = hp[1];
    __nv_bfloat162* pa = reinterpret_cast<__nv_bfloat162*>(&qa);
    __nv_bfloat162* pb = reinterpret_cast<__nv_bfloat162*>(&qb);
    float hv[16];
#pragma unroll
    for (int j = 0; j < 4; j++) {
        float2 f = __bfloat1622float2(pa[j]);
        hv[2 * j] = f.x; hv[2 * j + 1] = f.y;
        float2 g = __bfloat1622float2(pb[j]);
        hv[8 + 2 * j] = g.x; hv[8 + 2 * j + 1] = g.y;
    }
    float s0 = 0.f, s1 = 0.f, s2 = 0.f;
    const float4* ap0 = (const float4*)(att0 + base);
    const float4* ap1 = att1 ? (const float4*)(att1 + base) : nullptr;
    const float4* ap2 = att2 ? (const float4*)(att2 + base) : nullptr;
#pragma unroll
    for (int q = 0; q < 4; q++) {
        float4 av = ap0[q];
        s0 += hv[q*4]*av.x + hv[q*4+1]*av.y + hv[q*4+2]*av.z + hv[q*4+3]*av.w;
        if (ap1) {
            float4 bv = ap1[q];
            s1 += hv[q*4]*bv.x + hv[q*4+1]*bv.y + hv[q*4+2]*bv.z + hv[q*4+3]*bv.w;
        }
        if (ap2) {
            float4 cv = ap2[q];
            s2 += hv[q*4]*cv.x + hv[q*4+1]*cv.y + hv[q*4+2]*cv.z + hv[q*4+3]*cv.w;
        }
    }
#pragma unroll
    for (int d = 1; d <= 2; d <<= 1) {
        s0 += __shfl_xor_sync(0xffffffffu, s0, d);
        s1 += __shfl_xor_sync(0xffffffffu, s1, d);
        s2 += __shfl_xor_sync(0xffffffffu, s2, d);
    }
    if ((lane & 3) == 0) {
        int o = warp * HH + (lane >> 2);
        a0[o] = s0;
        if (a1) a1[o] = s1;
        if (a2) a2[o] = s2;
    }
}

// ---------------- edge pass 1: alpha + segment max + degree count -----------
__global__ void edge_alpha_max2(
        const int* __restrict__ s0p, const int* __restrict__ d0p,
        const int* __restrict__ s1p, const int* __restrict__ d1p,
        const float* __restrict__ ase, const float* __restrict__ ade,
        const float* __restrict__ aso, const float* __restrict__ ado,
        float* __restrict__ alpha, unsigned* __restrict__ amax,
        int* __restrict__ deg, int ne) {
    int i = blockIdx.x * blockDim.x + threadIdx.x;
    int half = ne * HH;
    if (i >= 2 * half) return;
    int m = i >= half;
    int li = m ? i - half : i;
    int e = li >> 3, h = li & 7;
    const int* sp = m ? s1p : s0p;
    const int* dp = m ? d1p : d0p;
    const float* as = m ? aso : ase;
    const float* ad = m ? ado : ade;
    int d = dp[e];
    float v = as[sp[e] * HH + h] + ad[d * HH + h];
    v = (v > 0.f) ? v : 0.2f * v;
    alpha[i] = v;
    atomicMax(&amax[m * NN * HH + d * HH + h], mapf(v));
    if (h == 0) atomicAdd(&deg[m * NN + d], 1);
}

// ---------------- edge pass 2: exp + segment sum ----------------------------
__global__ void edge_exp_sum2(
        const int* __restrict__ d0p, const int* __restrict__ d1p,
        float* __restrict__ alpha, const unsigned* __restrict__ amax,
        float* __restrict__ denom, int ne) {
    int i = blockIdx.x * blockDim.x + threadIdx.x;
    int half = ne * HH;
    if (i >= 2 * half) return;
    int m = i >= half;
    int li = m ? i - half : i;
    int e = li >> 3, h = li & 7;
    const int* dp = m ? d1p : d0p;
    int off = m * NN * HH + dp[e] * HH + h;
    float ex = expf(alpha[i] - unmapf(amax[off]));
    alpha[i] = ex;
    atomicAdd(&denom[off], ex);
}

// ---------------- CSR build: 3-kernel exclusive scan + fill -----------------
__global__ void scan1(const int* __restrict__ deg, int* __restrict__ startv,
                      int* __restrict__ bsum, int n) {
    __shared__ int sh[1024];
    int gid = blockIdx.x * 1024 + threadIdx.x;
    int v = (gid < n) ? deg[gid] : 0;
    sh[threadIdx.x] = v;
    __syncthreads();
    for (int off = 1; off < 1024; off <<= 1) {
        int t = (threadIdx.x >= off) ? sh[threadIdx.x - off] : 0;
        __syncthreads();
        sh[threadIdx.x] += t;
        __syncthreads();
    }
    if (gid < n) startv[gid] = sh[threadIdx.x] - v;
    if (threadIdx.x == 1023) bsum[blockIdx.x] = sh[1023];
}

__global__ void scan2(int* __restrict__ bsum, int nb) {
    __shared__ int sh[256];
    int v = (threadIdx.x < nb) ? bsum[threadIdx.x] : 0;
    sh[threadIdx.x] = v;
    __syncthreads();
    for (int off = 1; off < 256; off <<= 1) {
        int t = (threadIdx.x >= off) ? sh[threadIdx.x - off] : 0;
        __syncthreads();
        sh[threadIdx.x] += t;
        __syncthreads();
    }
    if (threadIdx.x < nb) bsum[threadIdx.x] = sh[threadIdx.x] - v;
}

__global__ void scan3(int* __restrict__ startv, const int* __restrict__ bsum,
                      int n) {
    int gid = blockIdx.x * 1024 + threadIdx.x;
    if (gid < n) startv[gid] += bsum[blockIdx.x];
}

__global__ void csr_fill(
        const int* __restrict__ s0p, const int* __restrict__ d0p,
        const int* __restrict__ s1p, const int* __restrict__ d1p,
        const int* __restrict__ startv, int* __restrict__ cur,
        int* __restrict__ eidx, int* __restrict__ esrc, int ne) {
    int i = blockIdx.x * blockDim.x + threadIdx.x;
    if (i >= 2 * ne) return;
    int m = i >= ne;
    int le = m ? i - ne : i;
    int d = m ? d1p[le] : d0p[le];
    int s = m ? s1p[le] : s0p[le];
    int dd = m * NN + d;
    int pos = startv[dd] + atomicAdd(&cur[dd], 1);
    eidx[pos] = i;       // merged edge index (matches ebuf layout)
    esrc[pos] = s;
}

// ---------------- gather: per-dst softmax-weighted sum, relu, bf16 ----------
__global__ void gather_conv(
        const int* __restrict__ eidx, const int* __restrict__ esrc,
        const int* __restrict__ startv, const int* __restrict__ deg,
        const __nv_bfloat16* __restrict__ h0,   // metapath 0 src feats (h_e)
        const __nv_bfloat16* __restrict__ h1,   // metapath 1 src feats (h_o)
        const float* __restrict__ ebuf, const float* __restrict__ denom,
        __nv_bfloat16* __restrict__ A0o, __nv_bfloat16* __restrict__ A1o) {
    int gw = (blockIdx.x * blockDim.x + threadIdx.x) >> 5;
    int lane = threadIdx.x & 31;
    if (gw >= 2 * NN) return;
    int m = gw >= NN;
    int d = gw - m * NN;
    const __nv_bfloat16* hs = m ? h1 : h0;
    __nv_bfloat16* outp = m ? A1o : A0o;
    int st = startv[gw];
    int de = deg[gw];
    int h = lane >> 2;
    float dinv = 1.0f / (denom[gw * HH + h] + 1e-16f);
    float acc[16];
#pragma unroll
    for (int q = 0; q < 16; q++) acc[q] = 0.f;

    for (int p = 0; p < de; p++) {
        int ge = eidx[st + p];
        int s  = esrc[st + p];
        float w = ebuf[ge * HH + h] * dinv;
        const uint4* hp = (const uint4*)(hs + (size_t)s * DD + lane * 16);
        uint4 qa = hp[0], qb = hp[1];
        __nv_bfloat162* pa = reinterpret_cast<__nv_bfloat162*>(&qa);
        __nv_bfloat162* pb = reinterpret_cast<__nv_bfloat162*>(&qb);
#pragma unroll
        for (int j = 0; j < 4; j++) {
            float2 f = __bfloat1622float2(pa[j]);
            acc[2 * j]     += f.x * w;
            acc[2 * j + 1] += f.y * w;
            float2 g = __bfloat1622float2(pb[j]);
            acc[8 + 2 * j]     += g.x * w;
            acc[8 + 2 * j + 1] += g.y * w;
        }
    }

    // relu + bf16 pack + store 32B
    uint4 o1, o2;
    unsigned* po = &o1.x;
#pragma unroll
    for (int j = 0; j < 8; j++) {
        float a = fmaxf(acc[2 * j], 0.f);
        float b = fmaxf(acc[2 * j + 1], 0.f);
        __nv_bfloat162 pk = __floats2bfloat162_rn(a, b);
        if (j < 4) po[j] = *reinterpret_cast<unsigned*>(&pk);
        else       (&o2.x)[j - 4] = *reinterpret_cast<unsigned*>(&pk);
    }
    uint4* dst = (uint4*)(outp + (size_t)d * DD + lane * 16);
    dst[0] = o1;
    dst[1] = o2;
}

// ---------------- final semantic attention + pool + linear ------------------
__global__ void final_kernel(const float* __restrict__ qsem,
                             const float* __restrict__ linw,
                             const float* __restrict__ linb,
                             float* __restrict__ out) {
    __shared__ float sh[DD];
    __shared__ float sv[2];
    int f = threadIdx.x;
    const float invN = 1.0f / (float)NN;
    float q = qsem[f];
    float v0 = g_ksum[f] * invN * q;
    float v1 = g_ksum[DD + f] * invN * q;

    sh[f] = v0; __syncthreads();
    for (int s = 256; s > 0; s >>= 1) { if (f < s) sh[f] += sh[f + s]; __syncthreads(); }
    if (f == 0) sv[0] = sh[0];
    __syncthreads();
    sh[f] = v1; __syncthreads();
    for (int s = 256; s > 0; s >>= 1) { if (f < s) sh[f] += sh[f + s]; __syncthreads(); }
    if (f == 0) sv[1] = sh[0];
    __syncthreads();

    float s0 = sv[0], s1 = sv[1];
    float mx = fmaxf(s0, s1);
    float e0 = expf(s0 - mx), e1 = expf(s1 - mx);
    float sem0 = e0 / (e0 + e1), sem1 = e1 / (e0 + e1);

    float pooled = (sem0 * g_musum[f] + sem1 * g_musum[DD + f]) * invN;
    float w0 = pooled * linw[f * 2 + 0];
    float w1 = pooled * linw[f * 2 + 1];

    sh[f] = w0; __syncthreads();
    for (int s = 256; s > 0; s >>= 1) { if (f < s) sh[f] += sh[f + s]; __syncthreads(); }
    if (f == 0) out[0] = sh[0] + linb[0];
    __syncthreads();
    sh[f] = w1; __syncthreads();
    for (int s = 256; s > 0; s >>= 1) { if (f < s) sh[f] += sh[f + s]; __syncthreads(); }
    if (f == 0) out[1] = sh[0] + linb[1];
}

// ---------------- host launcher ---------------------------------------------
extern "C" void kernel_launch(void* const* d_in, const int* in_sizes, int n_in,
                              void* d_out, int out_size) {
    const float* x_o  = (const float*)d_in[0];
    const float* x_e  = (const float*)d_in[1];
    const int*   e2o  = (const int*)d_in[2];
    const int*   o2o  = (const int*)d_in[3];
    const float* powm = (const float*)d_in[4];
    const float* pob  = (const float*)d_in[5];
    const float* pewm = (const float*)d_in[6];
    const float* peb  = (const float*)d_in[7];
    const float* a_s_e2o = (const float*)d_in[8];
    const float* a_d_e2o = (const float*)d_in[9];
    const float* a_s_o2o = (const float*)d_in[10];
    const float* a_d_o2o = (const float*)d_in[11];
    const float* klw  = (const float*)d_in[12];
    const float* klb  = (const float*)d_in[13];
    const float* qsem = (const float*)d_in[14];
    const float* linw = (const float*)d_in[15];
    const float* linb = (const float*)d_in[16];
    float* out = (float*)d_out;

    void* p;
    float *a_se, *a_de, *a_so, *a_do, *denom, *ebuf, *ksum, *musum;
    __nv_bfloat16 *hb_o, *hb_e, *Ab, *A0, *A1, *Wb;
    unsigned* amax;
    int *deg, *cur, *startv, *bsum, *eidx, *esrc;
    cudaGetSymbolAddress(&p, g_hb_o); hb_o = (__nv_bfloat16*)p;
    cudaGetSymbolAddress(&p, g_hb_e); hb_e = (__nv_bfloat16*)p;
    cudaGetSymbolAddress(&p, g_Ab);   Ab   = (__nv_bfloat16*)p;
    cudaGetSymbolAddress(&p, g_A0);   A0   = (__nv_bfloat16*)p;
    cudaGetSymbolAddress(&p, g_A1);   A1   = (__nv_bfloat16*)p;
    cudaGetSymbolAddress(&p, g_Wb);   Wb   = (__nv_bfloat16*)p;
    cudaGetSymbolAddress(&p, g_a_se); a_se = (float*)p;
    cudaGetSymbolAddress(&p, g_a_de); a_de = (float*)p;
    cudaGetSymbolAddress(&p, g_a_so); a_so = (float*)p;
    cudaGetSymbolAddress(&p, g_a_do); a_do = (float*)p;
    cudaGetSymbolAddress(&p, g_amax); amax = (unsigned*)p;
    cudaGetSymbolAddress(&p, g_denom); denom = (float*)p;
    cudaGetSymbolAddress(&p, g_ebuf); ebuf = (float*)p;
    cudaGetSymbolAddress(&p, g_deg);  deg  = (int*)p;
    cudaGetSymbolAddress(&p, g_cur);  cur  = (int*)p;
    cudaGetSymbolAddress(&p, g_startArr); startv = (int*)p;
    cudaGetSymbolAddress(&p, g_bsum); bsum = (int*)p;
    cudaGetSymbolAddress(&p, g_eidx); eidx = (int*)p;
    cudaGetSymbolAddress(&p, g_esrc); esrc = (int*)p;
    cudaGetSymbolAddress(&p, g_ksum); ksum = (float*)p;
    cudaGetSymbolAddress(&p, g_musum); musum = (float*)p;

    const long ND = (long)NN * DD;
    dim3 tcgrid(DD / GBN, (NN + GBM - 1) / GBM);   // (4, 782)
    const int NTOT = 2 * NN;                       // 200000
    const int SCAN_BLOCKS = (NTOT + 1023) / 1024;  // 196

    // ---- GEMM 1 as launch #4 (ncu capture point) ----
    conv_bf<<<256, 256>>>(powm, Wb, DD * DD);        // 1
    conv_bf<<<2048, 256>>>(x_o, Ab, ND);             // 2
    zero_buf<<<4, 256>>>(ksum, 2 * DD);              // 3
    gemm_bf<0><<<tcgrid, 256>>>(Ab, Wb, pob, hb_o, NN, nullptr);  // 4 PROFILED

    zero_buf<<<4, 256>>>(musum, 2 * DD);

    // ---- GEMM 2 ----
    conv_bf<<<256, 256>>>(pewm, Wb, DD * DD);
    conv_bf<<<2048, 256>>>(x_e, Ab, ND);
    gemm_bf<0><<<tcgrid, 256>>>(Ab, Wb, peb, hb_e, NN, nullptr);

    int ah_blocks = (NN * 32 + 255) / 256;
    int e2_blocks = (2 * EE * HH + 255) / 256;
    int ef_blocks = (2 * EE + 255) / 256;
    int ie_blocks = (2 * NN * HH + 255) / 256;
    int gw_blocks = (2 * NN * 32 + 255) / 256;

    // ---- attention dots ----
    compute_ah3<<<ah_blocks, 256>>>(hb_o, a_d_e2o, a_de, a_s_o2o, a_so, a_d_o2o, a_do, NN);
    compute_ah3<<<ah_blocks, 256>>>(hb_e, a_s_e2o, a_se, nullptr, nullptr, nullptr, nullptr, NN);

    // ---- edge passes + CSR build ----
    init_edge_state2<<<ie_blocks, 256>>>(amax, denom, deg, cur, 2 * NN * HH);
    edge_alpha_max2<<<e2_blocks, 256>>>(e2o, e2o + EE, o2o, o2o + EE,
                                        a_se, a_de, a_so, a_do, ebuf, amax, deg, EE);
    edge_exp_sum2<<<e2_blocks, 256>>>(e2o + EE, o2o + EE, ebuf, amax, denom, EE);
    scan1<<<SCAN_BLOCKS, 1024>>>(deg, startv, bsum, NTOT);
    scan2<<<1, 256>>>(bsum, SCAN_BLOCKS);
    scan3<<<SCAN_BLOCKS, 1024>>>(startv, bsum, NTOT);
    csr_fill<<<ef_blocks, 256>>>(e2o, e2o + EE, o2o, o2o + EE,
                                 startv, cur, eidx, esrc, EE);

    // ---- gather: softmax-weighted aggregation -> relu -> bf16 A0/A1 ----
    gather_conv<<<gw_blocks, 256>>>(eidx, esrc, startv, deg,
                                    hb_e, hb_o, ebuf, denom, A0, A1);

    // ---- semantic attention ----
    conv_bf<<<256, 256>>>(klw, Wb, DD * DD);
    mu_bf<<<128, 512>>>(A0, musum, NN);
    gemm_bf<1><<<tcgrid, 256>>>(A0, Wb, klb, nullptr, NN, ksum);
    mu_bf<<<128, 512>>>(A1, musum + DD, NN);
    gemm_bf<1><<<tcgrid, 256>>>(A1, Wb, klb, nullptr, NN, ksum + DD);

    // ---- softmax over metapaths, pool, final linear ----
    final_kernel<<<1, 512>>>(qsem, linw, linb, out);
}

// round 14
// speedup vs baseline: 2.1446x; 1.8389x over previous
#include <cuda_runtime.h>
#include <cuda_bf16.h>
#include <cstdint>
#include <math.h>
#include <mma.h>

using namespace nvcuda;

#define NN 100000
#define EE 150000
#define DD 512
#define HH 8

#define GBM 128
#define GBN 128
#define GBK 32
#define APADE 8
#define BPADE 8

// ---------------- scratch ---------------------------------------------------
__device__ __nv_bfloat16 g_hb_o[(size_t)NN * DD];
__device__ __nv_bfloat16 g_hb_e[(size_t)NN * DD];
__device__ __nv_bfloat16 g_Ab[(size_t)NN * DD];
__device__ __nv_bfloat16 g_Agg[(size_t)2 * NN * DD];   // both gathered metapaths
__device__ __nv_bfloat16 g_Wb[DD * DD];
__device__ float g_a_se[NN * HH];
__device__ float g_a_de[NN * HH];
__device__ float g_a_so[NN * HH];
__device__ float g_a_do[NN * HH];
__device__ unsigned g_amax[2 * NN * HH];
__device__ float g_denom[2 * NN * HH];
__device__ float g_ebuf[2 * EE * HH];
__device__ int g_deg[2 * NN];
__device__ int g_cur[2 * NN];
__device__ int g_startArr[2 * NN];
__device__ int g_bsum[256];
__device__ int g_eidx[2 * EE];
__device__ int g_esrc[2 * EE];
__device__ float g_ksum[2 * DD];
__device__ float g_musum[2 * DD];

// ---------------- helpers ---------------------------------------------------
__device__ __forceinline__ unsigned mapf(float f) {
    unsigned u = __float_as_uint(f);
    return (u & 0x80000000u) ? ~u : (u | 0x80000000u);
}
__device__ __forceinline__ float unmapf(unsigned u) {
    return __uint_as_float((u & 0x80000000u) ? (u & 0x7FFFFFFFu) : ~u);
}
__device__ __forceinline__ float tanha(float x) {
    float r;
    asm("tanh.approx.f32 %0, %1;" : "=f"(r) : "f"(x));
    return r;
}

__global__ void zero_buf(float* p, long n) {
    long i = (long)blockIdx.x * blockDim.x + threadIdx.x;
    long stride = (long)gridDim.x * blockDim.x;
    for (; i < n; i += stride) p[i] = 0.0f;
}

__global__ void init_edge_state2(unsigned* amax, float* denom, int* deg,
                                 int* cur, int n) {
    int i = blockIdx.x * blockDim.x + threadIdx.x;
    if (i < n) { amax[i] = 0x007FFFFFu; denom[i] = 0.0f; }
    if (i < 2 * NN) { deg[i] = 0; cur[i] = 0; }
}

// ---------------- fp32 -> bf16 ----------------------------------------------
__global__ void conv_bf(const float* __restrict__ src,
                        __nv_bfloat16* __restrict__ dst, long n) {
    long i = ((long)blockIdx.x * blockDim.x + threadIdx.x) * 4;
    long stride = (long)gridDim.x * blockDim.x * 4;
    for (; i < n; i += stride) {
        float4 v = *(const float4*)(src + i);
        *(__nv_bfloat162*)(dst + i)     = __floats2bfloat162_rn(v.x, v.y);
        *(__nv_bfloat162*)(dst + i + 2) = __floats2bfloat162_rn(v.z, v.w);
    }
}

// ---------------- column sums of fused bf16 matrix (2*NN rows) ---------------
__global__ void mu_bf2(const __nv_bfloat16* __restrict__ a,
                       float* __restrict__ musum) {
    int f = threadIdx.x;
    int M2 = 2 * NN;
    int chunk = (M2 + gridDim.x - 1) / gridDim.x;
    int r0 = blockIdx.x * chunk;
    int r1 = min(M2, r0 + chunk);
    float acc0 = 0.f, acc1 = 0.f;
    for (int r = r0; r < r1; r++) {
        float v = __bfloat162float(a[(size_t)r * DD + f]);
        if (r < NN) acc0 += v; else acc1 += v;
    }
    if (acc0 != 0.f) atomicAdd(&musum[f], acc0);
    if (acc1 != 0.f) atomicAdd(&musum[DD + f], acc1);
}

// ---------------- BF16 TC GEMM, 2-stage cp.async -----------------------------
// MODE 0: C = bf16(A@W + bias) stored.
// MODE 1: M = 2*NN fused; accumulates per-metapath sum_rows tanh(acc+bias)
//         into ksum_out[0..DD) (rows<NN) and ksum_out[DD..2DD) (rows>=NN).
template <int MODE>
__global__ void __launch_bounds__(256) gemm_bf(
        const __nv_bfloat16* __restrict__ A, const __nv_bfloat16* __restrict__ W,
        const float* __restrict__ bias, void* __restrict__ Cv, int M,
        float* __restrict__ ksum_out) {
    __shared__ __nv_bfloat16 As[2][GBM][GBK + APADE];
    __shared__ __nv_bfloat16 Bs[2][GBK][GBN + BPADE];
    __shared__ float stage[8][16][20];
    __shared__ float ksred[2][GBN];

    int tid = threadIdx.x;
    int wid = tid >> 5;
    int lane = tid & 31;
    int warp_m = wid & 3;
    int warp_n = wid >> 2;
    int m0 = blockIdx.y * GBM;
    int n0 = blockIdx.x * GBN;
    int wm0 = warp_m * 32;
    int wn0 = warp_n * 64;

    if (MODE == 1 && tid < GBN) { ksred[0][tid] = 0.0f; ksred[1][tid] = 0.0f; }

    auto load_stage = [&](int s, int k0) {
#pragma unroll
        for (int it = 0; it < 2; it++) {
            int idx = tid + it * 256;
            int ar = idx >> 2, ac = (idx & 3) * 8;
            int gm = m0 + ar;
            const __nv_bfloat16* srcA =
                A + (size_t)(gm < M ? gm : M - 1) * DD + k0 + ac;
            uint32_t dstA = (uint32_t)__cvta_generic_to_shared(&As[s][ar][ac]);
            int szA = (gm < M) ? 16 : 0;
            asm volatile("cp.async.cg.shared.global [%0], [%1], 16, %2;"
                         :: "r"(dstA), "l"(srcA), "r"(szA));
            int br = idx >> 4, bc = (idx & 15) * 8;
            const __nv_bfloat16* srcB = W + (size_t)(k0 + br) * DD + n0 + bc;
            uint32_t dstB = (uint32_t)__cvta_generic_to_shared(&Bs[s][br][bc]);
            asm volatile("cp.async.cg.shared.global [%0], [%1], 16, 16;"
                         :: "r"(dstB), "l"(srcB));
        }
        asm volatile("cp.async.commit_group;");
    };

    wmma::fragment<wmma::accumulator, 16, 16, 16, float> acc[2][4];
#pragma unroll
    for (int i = 0; i < 2; i++)
#pragma unroll
        for (int j = 0; j < 4; j++) wmma::fill_fragment(acc[i][j], 0.0f);

    load_stage(0, 0);

    int sbuf = 0;
    for (int k0 = 0; k0 < DD; k0 += GBK) {
        asm volatile("cp.async.wait_group 0;" ::: "memory");
        __syncthreads();
        if (k0 + GBK < DD) load_stage(sbuf ^ 1, k0 + GBK);

#pragma unroll
        for (int kk = 0; kk < GBK; kk += 16) {
            wmma::fragment<wmma::matrix_a, 16, 16, 16, __nv_bfloat16,
                           wmma::row_major> af[2];
            wmma::fragment<wmma::matrix_b, 16, 16, 16, __nv_bfloat16,
                           wmma::row_major> bf[4];
#pragma unroll
            for (int i = 0; i < 2; i++)
                wmma::load_matrix_sync(af[i], &As[sbuf][wm0 + i * 16][kk],
                                       GBK + APADE);
#pragma unroll
            for (int j = 0; j < 4; j++)
                wmma::load_matrix_sync(bf[j], &Bs[sbuf][kk][wn0 + j * 16],
                                       GBN + BPADE);
#pragma unroll
            for (int i = 0; i < 2; i++)
#pragma unroll
                for (int j = 0; j < 4; j++)
                    wmma::mma_sync(acc[i][j], af[i], bf[j], acc[i][j]);
        }
        sbuf ^= 1;
    }
    __syncthreads();

    int r = lane >> 1;
    int cbase = (lane & 1) * 8;
#pragma unroll
    for (int i = 0; i < 2; i++) {
#pragma unroll
        for (int j = 0; j < 4; j++) {
            wmma::store_matrix_sync(&stage[wid][0][0], acc[i][j], 20,
                                    wmma::mem_row_major);
            __syncwarp();
            int grow = m0 + wm0 + i * 16 + r;
            int gcol = n0 + wn0 + j * 16 + cbase;
            if (MODE == 0) {
                if (grow < M) {
                    float4 v1 = *(const float4*)(&stage[wid][r][cbase]);
                    float4 v2 = *(const float4*)(&stage[wid][r][cbase + 4]);
                    float4 b1 = *(const float4*)(bias + gcol);
                    float4 b2 = *(const float4*)(bias + gcol + 4);
                    v1.x += b1.x; v1.y += b1.y; v1.z += b1.z; v1.w += b1.w;
                    v2.x += b2.x; v2.y += b2.y; v2.z += b2.z; v2.w += b2.w;
                    __nv_bfloat162 r0 = __floats2bfloat162_rn(v1.x, v1.y);
                    __nv_bfloat162 r1 = __floats2bfloat162_rn(v1.z, v1.w);
                    __nv_bfloat162 r2 = __floats2bfloat162_rn(v2.x, v2.y);
                    __nv_bfloat162 r3 = __floats2bfloat162_rn(v2.z, v2.w);
                    uint4 ov;
                    ov.x = *reinterpret_cast<unsigned*>(&r0);
                    ov.y = *reinterpret_cast<unsigned*>(&r1);
                    ov.z = *reinterpret_cast<unsigned*>(&r2);
                    ov.w = *reinterpret_cast<unsigned*>(&r3);
                    *(uint4*)((__nv_bfloat16*)Cv + (size_t)grow * DD + gcol) = ov;
                }
            } else {
                // tanh + row-reduction across the 16 fragment rows
                float t[8];
                if (grow < M) {
                    float4 v1 = *(const float4*)(&stage[wid][r][cbase]);
                    float4 v2 = *(const float4*)(&stage[wid][r][cbase + 4]);
                    float4 b1 = *(const float4*)(bias + gcol);
                    float4 b2 = *(const float4*)(bias + gcol + 4);
                    t[0] = tanha(v1.x + b1.x); t[1] = tanha(v1.y + b1.y);
                    t[2] = tanha(v1.z + b1.z); t[3] = tanha(v1.w + b1.w);
                    t[4] = tanha(v2.x + b2.x); t[5] = tanha(v2.y + b2.y);
                    t[6] = tanha(v2.z + b2.z); t[7] = tanha(v2.w + b2.w);
                } else {
#pragma unroll
                    for (int q = 0; q < 8; q++) t[q] = 0.f;
                }
#pragma unroll
                for (int d = 2; d <= 16; d <<= 1)
#pragma unroll
                    for (int q = 0; q < 8; q++)
                        t[q] += __shfl_xor_sync(0xffffffffu, t[q], d);
                // fragment rows all on one side of NN (16 | NN)
                int bank = (m0 + wm0 + i * 16) >= NN;
                if (lane < 2) {
                    int lc = wn0 + j * 16 + lane * 8;
#pragma unroll
                    for (int q = 0; q < 8; q++)
                        atomicAdd(&ksred[bank][lc + q], t[q]);
                }
            }
            __syncwarp();
        }
    }
    if (MODE == 1) {
        __syncthreads();
        if (tid < GBN) {
            atomicAdd(&ksum_out[n0 + tid], ksred[0][tid]);
            atomicAdd(&ksum_out[DD + n0 + tid], ksred[1][tid]);
        }
    }
}

// ---------------- attention dots from bf16 h --------------------------------
__global__ void compute_ah3(const __nv_bfloat16* __restrict__ hmat,
                            const float* __restrict__ att0, float* __restrict__ a0,
                            const float* __restrict__ att1, float* __restrict__ a1,
                            const float* __restrict__ att2, float* __restrict__ a2,
                            int n_nodes) {
    int gt = blockIdx.x * blockDim.x + threadIdx.x;
    int warp = gt >> 5;
    int lane = threadIdx.x & 31;
    if (warp >= n_nodes) return;
    int base = lane * 16;
    const uint4* hp = (const uint4*)(hmat + (size_t)warp * DD + base);
    uint4 qa = hp[0], qb = hp[1];
    __nv_bfloat162* pa = reinterpret_cast<__nv_bfloat162*>(&qa);
    __nv_bfloat162* pb = reinterpret_cast<__nv_bfloat162*>(&qb);
    float hv[16];
#pragma unroll
    for (int j = 0; j < 4; j++) {
        float2 f = __bfloat1622float2(pa[j]);
        hv[2 * j] = f.x; hv[2 * j + 1] = f.y;
        float2 g = __bfloat1622float2(pb[j]);
        hv[8 + 2 * j] = g.x; hv[8 + 2 * j + 1] = g.y;
    }
    float s0 = 0.f, s1 = 0.f, s2 = 0.f;
    const float4* ap0 = (const float4*)(att0 + base);
    const float4* ap1 = att1 ? (const float4*)(att1 + base) : nullptr;
    const float4* ap2 = att2 ? (const float4*)(att2 + base) : nullptr;
#pragma unroll
    for (int q = 0; q < 4; q++) {
        float4 av = ap0[q];
        s0 += hv[q*4]*av.x + hv[q*4+1]*av.y + hv[q*4+2]*av.z + hv[q*4+3]*av.w;
        if (ap1) {
            float4 bv = ap1[q];
            s1 += hv[q*4]*bv.x + hv[q*4+1]*bv.y + hv[q*4+2]*bv.z + hv[q*4+3]*bv.w;
        }
        if (ap2) {
            float4 cv = ap2[q];
            s2 += hv[q*4]*cv.x + hv[q*4+1]*cv.y + hv[q*4+2]*cv.z + hv[q*4+3]*cv.w;
        }
    }
#pragma unroll
    for (int d = 1; d <= 2; d <<= 1) {
        s0 += __shfl_xor_sync(0xffffffffu, s0, d);
        s1 += __shfl_xor_sync(0xffffffffu, s1, d);
        s2 += __shfl_xor_sync(0xffffffffu, s2, d);
    }
    if ((lane & 3) == 0) {
        int o = warp * HH + (lane >> 2);
        a0[o] = s0;
        if (a1) a1[o] = s1;
        if (a2) a2[o] = s2;
    }
}

// ---------------- edge pass 1: alpha + segment max + degree -----------------
__global__ void edge_alpha_max2(
        const int* __restrict__ s0p, const int* __restrict__ d0p,
        const int* __restrict__ s1p, const int* __restrict__ d1p,
        const float* __restrict__ ase, const float* __restrict__ ade,
        const float* __restrict__ aso, const float* __restrict__ ado,
        float* __restrict__ alpha, unsigned* __restrict__ amax,
        int* __restrict__ deg, int ne) {
    int i = blockIdx.x * blockDim.x + threadIdx.x;
    int half = ne * HH;
    if (i >= 2 * half) return;
    int m = i >= half;
    int li = m ? i - half : i;
    int e = li >> 3, h = li & 7;
    const int* sp = m ? s1p : s0p;
    const int* dp = m ? d1p : d0p;
    const float* as = m ? aso : ase;
    const float* ad = m ? ado : ade;
    int d = dp[e];
    float v = as[sp[e] * HH + h] + ad[d * HH + h];
    v = (v > 0.f) ? v : 0.2f * v;
    alpha[i] = v;
    atomicMax(&amax[m * NN * HH + d * HH + h], mapf(v));
    if (h == 0) atomicAdd(&deg[m * NN + d], 1);
}

// ---------------- edge pass 2: exp + segment sum ----------------------------
__global__ void edge_exp_sum2(
        const int* __restrict__ d0p, const int* __restrict__ d1p,
        float* __restrict__ alpha, const unsigned* __restrict__ amax,
        float* __restrict__ denom, int ne) {
    int i = blockIdx.x * blockDim.x + threadIdx.x;
    int half = ne * HH;
    if (i >= 2 * half) return;
    int m = i >= half;
    int li = m ? i - half : i;
    int e = li >> 3, h = li & 7;
    const int* dp = m ? d1p : d0p;
    int off = m * NN * HH + dp[e] * HH + h;
    float ex = expf(alpha[i] - unmapf(amax[off]));
    alpha[i] = ex;
    atomicAdd(&denom[off], ex);
}

// ---------------- CSR build -------------------------------------------------
__global__ void scan1(const int* __restrict__ deg, int* __restrict__ startv,
                      int* __restrict__ bsum, int n) {
    __shared__ int sh[1024];
    int gid = blockIdx.x * 1024 + threadIdx.x;
    int v = (gid < n) ? deg[gid] : 0;
    sh[threadIdx.x] = v;
    __syncthreads();
    for (int off = 1; off < 1024; off <<= 1) {
        int t = (threadIdx.x >= off) ? sh[threadIdx.x - off] : 0;
        __syncthreads();
        sh[threadIdx.x] += t;
        __syncthreads();
    }
    if (gid < n) startv[gid] = sh[threadIdx.x] - v;
    if (threadIdx.x == 1023) bsum[blockIdx.x] = sh[1023];
}

__global__ void scan2(int* __restrict__ bsum, int nb) {
    __shared__ int sh[256];
    int v = (threadIdx.x < nb) ? bsum[threadIdx.x] : 0;
    sh[threadIdx.x] = v;
    __syncthreads();
    for (int off = 1; off < 256; off <<= 1) {
        int t = (threadIdx.x >= off) ? sh[threadIdx.x - off] : 0;
        __syncthreads();
        sh[threadIdx.x] += t;
        __syncthreads();
    }
    if (threadIdx.x < nb) bsum[threadIdx.x] = sh[threadIdx.x] - v;
}

__global__ void scan3(int* __restrict__ startv, const int* __restrict__ bsum,
                      int n) {
    int gid = blockIdx.x * 1024 + threadIdx.x;
    if (gid < n) startv[gid] += bsum[blockIdx.x];
}

__global__ void csr_fill(
        const int* __restrict__ s0p, const int* __restrict__ d0p,
        const int* __restrict__ s1p, const int* __restrict__ d1p,
        const int* __restrict__ startv, int* __restrict__ cur,
        int* __restrict__ eidx, int* __restrict__ esrc, int ne) {
    int i = blockIdx.x * blockDim.x + threadIdx.x;
    if (i >= 2 * ne) return;
    int m = i >= ne;
    int le = m ? i - ne : i;
    int d = m ? d1p[le] : d0p[le];
    int s = m ? s1p[le] : s0p[le];
    int dd = m * NN + d;
    int pos = startv[dd] + atomicAdd(&cur[dd], 1);
    eidx[pos] = i;
    esrc[pos] = s;
}

// ---------------- gather: per-dst weighted sum -> relu -> bf16 Agg ----------
__global__ void gather_conv(
        const int* __restrict__ eidx, const int* __restrict__ esrc,
        const int* __restrict__ startv, const int* __restrict__ deg,
        const __nv_bfloat16* __restrict__ h0,
        const __nv_bfloat16* __restrict__ h1,
        const float* __restrict__ ebuf, const float* __restrict__ denom,
        __nv_bfloat16* __restrict__ Agg) {
    int gw = (blockIdx.x * blockDim.x + threadIdx.x) >> 5;
    int lane = threadIdx.x & 31;
    if (gw >= 2 * NN) return;
    int m = gw >= NN;
    const __nv_bfloat16* hs = m ? h1 : h0;
    int st = startv[gw];
    int de = deg[gw];
    int h = lane >> 2;
    float dinv = 1.0f / (denom[gw * HH + h] + 1e-16f);
    float acc[16];
#pragma unroll
    for (int q = 0; q < 16; q++) acc[q] = 0.f;

    for (int p = 0; p < de; p++) {
        int ge = eidx[st + p];
        int s  = esrc[st + p];
        float w = ebuf[ge * HH + h] * dinv;
        const uint4* hp = (const uint4*)(hs + (size_t)s * DD + lane * 16);
        uint4 qa = hp[0], qb = hp[1];
        __nv_bfloat162* pa = reinterpret_cast<__nv_bfloat162*>(&qa);
        __nv_bfloat162* pb = reinterpret_cast<__nv_bfloat162*>(&qb);
#pragma unroll
        for (int j = 0; j < 4; j++) {
            float2 f = __bfloat1622float2(pa[j]);
            acc[2 * j]     += f.x * w;
            acc[2 * j + 1] += f.y * w;
            float2 g = __bfloat1622float2(pb[j]);
            acc[8 + 2 * j]     += g.x * w;
            acc[8 + 2 * j + 1] += g.y * w;
        }
    }

    uint4 o1, o2;
#pragma unroll
    for (int j = 0; j < 8; j++) {
        float a = fmaxf(acc[2 * j], 0.f);
        float b = fmaxf(acc[2 * j + 1], 0.f);
        __nv_bfloat162 pk = __floats2bfloat162_rn(a, b);
        if (j < 4) (&o1.x)[j] = *reinterpret_cast<unsigned*>(&pk);
        else       (&o2.x)[j - 4] = *reinterpret_cast<unsigned*>(&pk);
    }
    uint4* dst = (uint4*)(Agg + (size_t)gw * DD + lane * 16);
    dst[0] = o1;
    dst[1] = o2;
}

// ---------------- final semantic attention + pool + linear ------------------
__global__ void final_kernel(const float* __restrict__ qsem,
                             const float* __restrict__ linw,
                             const float* __restrict__ linb,
                             float* __restrict__ out) {
    __shared__ float sh[DD];
    __shared__ float sv[2];
    int f = threadIdx.x;
    const float invN = 1.0f / (float)NN;
    float q = qsem[f];
    float v0 = g_ksum[f] * invN * q;
    float v1 = g_ksum[DD + f] * invN * q;

    sh[f] = v0; __syncthreads();
    for (int s = 256; s > 0; s >>= 1) { if (f < s) sh[f] += sh[f + s]; __syncthreads(); }
    if (f == 0) sv[0] = sh[0];
    __syncthreads();
    sh[f] = v1; __syncthreads();
    for (int s = 256; s > 0; s >>= 1) { if (f < s) sh[f] += sh[f + s]; __syncthreads(); }
    if (f == 0) sv[1] = sh[0];
    __syncthreads();

    float s0 = sv[0], s1 = sv[1];
    float mx = fmaxf(s0, s1);
    float e0 = expf(s0 - mx), e1 = expf(s1 - mx);
    float sem0 = e0 / (e0 + e1), sem1 = e1 / (e0 + e1);

    float pooled = (sem0 * g_musum[f] + sem1 * g_musum[DD + f]) * invN;
    float w0 = pooled * linw[f * 2 + 0];
    float w1 = pooled * linw[f * 2 + 1];

    sh[f] = w0; __syncthreads();
    for (int s = 256; s > 0; s >>= 1) { if (f < s) sh[f] += sh[f + s]; __syncthreads(); }
    if (f == 0) out[0] = sh[0] + linb[0];
    __syncthreads();
    sh[f] = w1; __syncthreads();
    for (int s = 256; s > 0; s >>= 1) { if (f < s) sh[f] += sh[f + s]; __syncthreads(); }
    if (f == 0) out[1] = sh[0] + linb[1];
}

// ---------------- host launcher ---------------------------------------------
extern "C" void kernel_launch(void* const* d_in, const int* in_sizes, int n_in,
                              void* d_out, int out_size) {
    const float* x_o  = (const float*)d_in[0];
    const float* x_e  = (const float*)d_in[1];
    const int*   e2o  = (const int*)d_in[2];
    const int*   o2o  = (const int*)d_in[3];
    const float* powm = (const float*)d_in[4];
    const float* pob  = (const float*)d_in[5];
    const float* pewm = (const float*)d_in[6];
    const float* peb  = (const float*)d_in[7];
    const float* a_s_e2o = (const float*)d_in[8];
    const float* a_d_e2o = (const float*)d_in[9];
    const float* a_s_o2o = (const float*)d_in[10];
    const float* a_d_o2o = (const float*)d_in[11];
    const float* klw  = (const float*)d_in[12];
    const float* klb  = (const float*)d_in[13];
    const float* qsem = (const float*)d_in[14];
    const float* linw = (const float*)d_in[15];
    const float* linb = (const float*)d_in[16];
    float* out = (float*)d_out;

    void* p;
    float *a_se, *a_de, *a_so, *a_do, *denom, *ebuf, *ksum, *musum;
    __nv_bfloat16 *hb_o, *hb_e, *Ab, *Agg, *Wb;
    unsigned* amax;
    int *deg, *cur, *startv, *bsum, *eidx, *esrc;
    cudaGetSymbolAddress(&p, g_hb_o); hb_o = (__nv_bfloat16*)p;
    cudaGetSymbolAddress(&p, g_hb_e); hb_e = (__nv_bfloat16*)p;
    cudaGetSymbolAddress(&p, g_Ab);   Ab   = (__nv_bfloat16*)p;
    cudaGetSymbolAddress(&p, g_Agg);  Agg  = (__nv_bfloat16*)p;
    cudaGetSymbolAddress(&p, g_Wb);   Wb   = (__nv_bfloat16*)p;
    cudaGetSymbolAddress(&p, g_a_se); a_se = (float*)p;
    cudaGetSymbolAddress(&p, g_a_de); a_de = (float*)p;
    cudaGetSymbolAddress(&p, g_a_so); a_so = (float*)p;
    cudaGetSymbolAddress(&p, g_a_do); a_do = (float*)p;
    cudaGetSymbolAddress(&p, g_amax); amax = (unsigned*)p;
    cudaGetSymbolAddress(&p, g_denom); denom = (float*)p;
    cudaGetSymbolAddress(&p, g_ebuf); ebuf = (float*)p;
    cudaGetSymbolAddress(&p, g_deg);  deg  = (int*)p;
    cudaGetSymbolAddress(&p, g_cur);  cur  = (int*)p;
    cudaGetSymbolAddress(&p, g_startArr); startv = (int*)p;
    cudaGetSymbolAddress(&p, g_bsum); bsum = (int*)p;
    cudaGetSymbolAddress(&p, g_eidx); eidx = (int*)p;
    cudaGetSymbolAddress(&p, g_esrc); esrc = (int*)p;
    cudaGetSymbolAddress(&p, g_ksum); ksum = (float*)p;
    cudaGetSymbolAddress(&p, g_musum); musum = (float*)p;

    const long ND = (long)NN * DD;
    dim3 tcgrid(DD / GBN, (NN + GBM - 1) / GBM);        // (4, 782)
    dim3 tcgrid2(DD / GBN, (2 * NN + GBM - 1) / GBM);   // (4, 1563)
    const int NTOT = 2 * NN;
    const int SCAN_BLOCKS = (NTOT + 1023) / 1024;

    // ---- GEMM 1 as launch #4 (ncu capture point) ----
    conv_bf<<<256, 256>>>(powm, Wb, DD * DD);
    conv_bf<<<2048, 256>>>(x_o, Ab, ND);
    zero_buf<<<4, 256>>>(ksum, 2 * DD);
    gemm_bf<0><<<tcgrid, 256>>>(Ab, Wb, pob, hb_o, NN, nullptr);  // PROFILED

    zero_buf<<<4, 256>>>(musum, 2 * DD);

    // ---- GEMM 2 ----
    conv_bf<<<256, 256>>>(pewm, Wb, DD * DD);
    conv_bf<<<2048, 256>>>(x_e, Ab, ND);
    gemm_bf<0><<<tcgrid, 256>>>(Ab, Wb, peb, hb_e, NN, nullptr);

    int ah_blocks = (NN * 32 + 255) / 256;
    int e2_blocks = (2 * EE * HH + 255) / 256;
    int ef_blocks = (2 * EE + 255) / 256;
    int ie_blocks = (2 * NN * HH + 255) / 256;
    int gw_blocks = (2 * NN * 32 + 255) / 256;

    // ---- attention dots ----
    compute_ah3<<<ah_blocks, 256>>>(hb_o, a_d_e2o, a_de, a_s_o2o, a_so, a_d_o2o, a_do, NN);
    compute_ah3<<<ah_blocks, 256>>>(hb_e, a_s_e2o, a_se, nullptr, nullptr, nullptr, nullptr, NN);

    // ---- edge passes + CSR ----
    init_edge_state2<<<ie_blocks, 256>>>(amax, denom, deg, cur, 2 * NN * HH);
    edge_alpha_max2<<<e2_blocks, 256>>>(e2o, e2o + EE, o2o, o2o + EE,
                                        a_se, a_de, a_so, a_do, ebuf, amax, deg, EE);
    edge_exp_sum2<<<e2_blocks, 256>>>(e2o + EE, o2o + EE, ebuf, amax, denom, EE);
    scan1<<<SCAN_BLOCKS, 1024>>>(deg, startv, bsum, NTOT);
    scan2<<<1, 256>>>(bsum, SCAN_BLOCKS);
    scan3<<<SCAN_BLOCKS, 1024>>>(startv, bsum, NTOT);
    csr_fill<<<ef_blocks, 256>>>(e2o, e2o + EE, o2o, o2o + EE,
                                 startv, cur, eidx, esrc, EE);

    // ---- gather -> Agg (both metapaths) ----
    gather_conv<<<gw_blocks, 256>>>(eidx, esrc, startv, deg,
                                    hb_e, hb_o, ebuf, denom, Agg);

    // ---- semantic attention: fused mu + single M=2NN GEMM ----
    conv_bf<<<256, 256>>>(klw, Wb, DD * DD);
    mu_bf2<<<256, 512>>>(Agg, musum);
    gemm_bf<1><<<tcgrid2, 256>>>(Agg, Wb, klb, nullptr, 2 * NN, ksum);

    // ---- softmax over metapaths, pool, final linear ----
    final_kernel<<<1, 512>>>(qsem, linw, linb, out);
}

// round 15
// speedup vs baseline: 2.3350x; 1.0888x over previous
#include <cuda_runtime.h>
#include <cuda_bf16.h>
#include <cstdint>
#include <math.h>
#include <mma.h>

using namespace nvcuda;

#define NN 100000
#define EE 150000
#define DD 512
#define HH 8

#define GBM 128
#define GBN 128
#define GBK 32
#define APADE 8
#define BPADE 8

// ---------------- scratch ---------------------------------------------------
__device__ __nv_bfloat16 g_hb_o[(size_t)NN * DD];
__device__ __nv_bfloat16 g_hb_e[(size_t)NN * DD];
__device__ __nv_bfloat16 g_Ab[(size_t)NN * DD];
__device__ __nv_bfloat16 g_Agg[(size_t)2 * NN * DD];
__device__ __nv_bfloat16 g_Wb[DD * DD];
__device__ float g_a_se[NN * HH];
__device__ float g_a_de[NN * HH];
__device__ float g_a_so[NN * HH];
__device__ float g_a_do[NN * HH];
__device__ unsigned g_amax[2 * NN * HH];
__device__ float g_denom[2 * NN * HH];
__device__ float g_ebuf[2 * EE * HH];
__device__ int g_deg[2 * NN];
__device__ int g_cur[2 * NN];
__device__ int g_startArr[2 * NN];
__device__ int g_ind[2 * NN];
__device__ int g_nzpos[2 * NN];
__device__ int g_bsum[256];
__device__ int g_bsum2[256];
__device__ int g_meta[4];     // {nz0, P0, M1, NN-nz1}
__device__ int g_eidx[2 * EE];
__device__ int g_esrc[2 * EE];
__device__ float g_ksum[2 * DD];
__device__ float g_musum[2 * DD];

// ---------------- helpers ---------------------------------------------------
__device__ __forceinline__ unsigned mapf(float f) {
    unsigned u = __float_as_uint(f);
    return (u & 0x80000000u) ? ~u : (u | 0x80000000u);
}
__device__ __forceinline__ float unmapf(unsigned u) {
    return __uint_as_float((u & 0x80000000u) ? (u & 0x7FFFFFFFu) : ~u);
}
__device__ __forceinline__ float tanha(float x) {
    float r;
    asm("tanh.approx.f32 %0, %1;" : "=f"(r) : "f"(x));
    return r;
}

__global__ void zero_buf(float* p, long n) {
    long i = (long)blockIdx.x * blockDim.x + threadIdx.x;
    long stride = (long)gridDim.x * blockDim.x;
    for (; i < n; i += stride) p[i] = 0.0f;
}

__global__ void init_edge_state2(unsigned* amax, float* denom, int* deg,
                                 int* cur, int n) {
    int i = blockIdx.x * blockDim.x + threadIdx.x;
    if (i < n) { amax[i] = 0x007FFFFFu; denom[i] = 0.0f; }
    if (i < 2 * NN) { deg[i] = 0; cur[i] = 0; }
}

// ---------------- fp32 -> bf16 ----------------------------------------------
__global__ void conv_bf(const float* __restrict__ src,
                        __nv_bfloat16* __restrict__ dst, long n) {
    long i = ((long)blockIdx.x * blockDim.x + threadIdx.x) * 4;
    long stride = (long)gridDim.x * blockDim.x * 4;
    for (; i < n; i += stride) {
        float4 v = *(const float4*)(src + i);
        *(__nv_bfloat162*)(dst + i)     = __floats2bfloat162_rn(v.x, v.y);
        *(__nv_bfloat162*)(dst + i + 2) = __floats2bfloat162_rn(v.z, v.w);
    }
}

// ---------------- column sums of compacted Agg -------------------------------
__global__ void mu_bf2(const __nv_bfloat16* __restrict__ a,
                       float* __restrict__ musum, const int* __restrict__ meta) {
    int f = threadIdx.x;
    int P0 = meta[1], M1 = meta[2];
    int chunk = (2 * NN + gridDim.x - 1) / gridDim.x;
    int r0 = blockIdx.x * chunk;
    int r1 = min(M1, r0 + chunk);
    float acc0 = 0.f, acc1 = 0.f;
    for (int r = r0; r < r1; r++) {
        float v = __bfloat162float(a[(size_t)r * DD + f]);
        if (r < P0) acc0 += v; else acc1 += v;
    }
    if (acc0 != 0.f) atomicAdd(&musum[f], acc0);
    if (acc1 != 0.f) atomicAdd(&musum[DD + f], acc1);
}

// ---------------- BF16 TC GEMM, 2-stage cp.async -----------------------------
// MODE 0: C = bf16(A@W + bias), M given.
// MODE 1: M and metapath boundary read from meta; per-block bank (P0 is
//         128-aligned); accumulates sum_rows tanh(acc+bias) into ksum_out.
template <int MODE>
__global__ void __launch_bounds__(256) gemm_bf(
        const __nv_bfloat16* __restrict__ A, const __nv_bfloat16* __restrict__ W,
        const float* __restrict__ bias, void* __restrict__ Cv, int M,
        float* __restrict__ ksum_out, const int* __restrict__ meta) {
    __shared__ __nv_bfloat16 As[2][GBM][GBK + APADE];
    __shared__ __nv_bfloat16 Bs[2][GBK][GBN + BPADE];
    __shared__ float stage[8][16][20];
    __shared__ float ksred[GBN];

    int m0 = blockIdx.y * GBM;
    int bank = 0;
    if (MODE == 1) {
        int Mv = meta[2];
        if (m0 >= Mv) return;
        M = Mv;
        bank = (m0 >= meta[1]) ? 1 : 0;
    }

    int tid = threadIdx.x;
    int wid = tid >> 5;
    int lane = tid & 31;
    int warp_m = wid & 3;
    int warp_n = wid >> 2;
    int n0 = blockIdx.x * GBN;
    int wm0 = warp_m * 32;
    int wn0 = warp_n * 64;

    if (MODE == 1 && tid < GBN) ksred[tid] = 0.0f;

    auto load_stage = [&](int s, int k0) {
#pragma unroll
        for (int it = 0; it < 2; it++) {
            int idx = tid + it * 256;
            int ar = idx >> 2, ac = (idx & 3) * 8;
            int gm = m0 + ar;
            const __nv_bfloat16* srcA =
                A + (size_t)(gm < M ? gm : M - 1) * DD + k0 + ac;
            uint32_t dstA = (uint32_t)__cvta_generic_to_shared(&As[s][ar][ac]);
            asm volatile("cp.async.cg.shared.global [%0], [%1], 16, 16;"
                         :: "r"(dstA), "l"(srcA));
            int br = idx >> 4, bc = (idx & 15) * 8;
            const __nv_bfloat16* srcB = W + (size_t)(k0 + br) * DD + n0 + bc;
            uint32_t dstB = (uint32_t)__cvta_generic_to_shared(&Bs[s][br][bc]);
            asm volatile("cp.async.cg.shared.global [%0], [%1], 16, 16;"
                         :: "r"(dstB), "l"(srcB));
        }
        asm volatile("cp.async.commit_group;");
    };

    wmma::fragment<wmma::accumulator, 16, 16, 16, float> acc[2][4];
#pragma unroll
    for (int i = 0; i < 2; i++)
#pragma unroll
        for (int j = 0; j < 4; j++) wmma::fill_fragment(acc[i][j], 0.0f);

    load_stage(0, 0);

    int sbuf = 0;
    for (int k0 = 0; k0 < DD; k0 += GBK) {
        asm volatile("cp.async.wait_group 0;" ::: "memory");
        __syncthreads();
        if (k0 + GBK < DD) load_stage(sbuf ^ 1, k0 + GBK);

#pragma unroll
        for (int kk = 0; kk < GBK; kk += 16) {
            wmma::fragment<wmma::matrix_a, 16, 16, 16, __nv_bfloat16,
                           wmma::row_major> af[2];
            wmma::fragment<wmma::matrix_b, 16, 16, 16, __nv_bfloat16,
                           wmma::row_major> bf[4];
#pragma unroll
            for (int i = 0; i < 2; i++)
                wmma::load_matrix_sync(af[i], &As[sbuf][wm0 + i * 16][kk],
                                       GBK + APADE);
#pragma unroll
            for (int j = 0; j < 4; j++)
                wmma::load_matrix_sync(bf[j], &Bs[sbuf][kk][wn0 + j * 16],
                                       GBN + BPADE);
#pragma unroll
            for (int i = 0; i < 2; i++)
#pragma unroll
                for (int j = 0; j < 4; j++)
                    wmma::mma_sync(acc[i][j], af[i], bf[j], acc[i][j]);
        }
        sbuf ^= 1;
    }
    __syncthreads();

    int r = lane >> 1;
    int cbase = (lane & 1) * 8;
#pragma unroll
    for (int i = 0; i < 2; i++) {
#pragma unroll
        for (int j = 0; j < 4; j++) {
            wmma::store_matrix_sync(&stage[wid][0][0], acc[i][j], 20,
                                    wmma::mem_row_major);
            __syncwarp();
            int grow = m0 + wm0 + i * 16 + r;
            int gcol = n0 + wn0 + j * 16 + cbase;
            if (MODE == 0) {
                if (grow < M) {
                    float4 v1 = *(const float4*)(&stage[wid][r][cbase]);
                    float4 v2 = *(const float4*)(&stage[wid][r][cbase + 4]);
                    float4 b1 = *(const float4*)(bias + gcol);
                    float4 b2 = *(const float4*)(bias + gcol + 4);
                    v1.x += b1.x; v1.y += b1.y; v1.z += b1.z; v1.w += b1.w;
                    v2.x += b2.x; v2.y += b2.y; v2.z += b2.z; v2.w += b2.w;
                    __nv_bfloat162 r0 = __floats2bfloat162_rn(v1.x, v1.y);
                    __nv_bfloat162 r1 = __floats2bfloat162_rn(v1.z, v1.w);
                    __nv_bfloat162 r2 = __floats2bfloat162_rn(v2.x, v2.y);
                    __nv_bfloat162 r3 = __floats2bfloat162_rn(v2.z, v2.w);
                    uint4 ov;
                    ov.x = *reinterpret_cast<unsigned*>(&r0);
                    ov.y = *reinterpret_cast<unsigned*>(&r1);
                    ov.z = *reinterpret_cast<unsigned*>(&r2);
                    ov.w = *reinterpret_cast<unsigned*>(&r3);
                    *(uint4*)((__nv_bfloat16*)Cv + (size_t)grow * DD + gcol) = ov;
                }
            } else {
                float t[8];
                if (grow < M) {
                    float4 v1 = *(const float4*)(&stage[wid][r][cbase]);
                    float4 v2 = *(const float4*)(&stage[wid][r][cbase + 4]);
                    float4 b1 = *(const float4*)(bias + gcol);
                    float4 b2 = *(const float4*)(bias + gcol + 4);
                    t[0] = tanha(v1.x + b1.x); t[1] = tanha(v1.y + b1.y);
                    t[2] = tanha(v1.z + b1.z); t[3] = tanha(v1.w + b1.w);
                    t[4] = tanha(v2.x + b2.x); t[5] = tanha(v2.y + b2.y);
                    t[6] = tanha(v2.z + b2.z); t[7] = tanha(v2.w + b2.w);
                } else {
#pragma unroll
                    for (int q = 0; q < 8; q++) t[q] = 0.f;
                }
#pragma unroll
                for (int d = 2; d <= 16; d <<= 1)
#pragma unroll
                    for (int q = 0; q < 8; q++)
                        t[q] += __shfl_xor_sync(0xffffffffu, t[q], d);
                if (lane < 2) {
                    int lc = wn0 + j * 16 + lane * 8;
#pragma unroll
                    for (int q = 0; q < 8; q++)
                        atomicAdd(&ksred[lc + q], t[q]);
                }
            }
            __syncwarp();
        }
    }
    if (MODE == 1) {
        __syncthreads();
        if (tid < GBN)
            atomicAdd(&ksum_out[bank * DD + n0 + tid], ksred[tid]);
    }
}

// ---------------- attention dots from bf16 h --------------------------------
__global__ void compute_ah3(const __nv_bfloat16* __restrict__ hmat,
                            const float* __restrict__ att0, float* __restrict__ a0,
                            const float* __restrict__ att1, float* __restrict__ a1,
                            const float* __restrict__ att2, float* __restrict__ a2,
                            int n_nodes) {
    int gt = blockIdx.x * blockDim.x + threadIdx.x;
    int warp = gt >> 5;
    int lane = threadIdx.x & 31;
    if (warp >= n_nodes) return;
    int base = lane * 16;
    const uint4* hp = (const uint4*)(hmat + (size_t)warp * DD + base);
    uint4 qa = hp[0], qb = hp[1];
    __nv_bfloat162* pa = reinterpret_cast<__nv_bfloat162*>(&qa);
    __nv_bfloat162* pb = reinterpret_cast<__nv_bfloat162*>(&qb);
    float hv[16];
#pragma unroll
    for (int j = 0; j < 4; j++) {
        float2 f = __bfloat1622float2(pa[j]);
        hv[2 * j] = f.x; hv[2 * j + 1] = f.y;
        float2 g = __bfloat1622float2(pb[j]);
        hv[8 + 2 * j] = g.x; hv[8 + 2 * j + 1] = g.y;
    }
    float s0 = 0.f, s1 = 0.f, s2 = 0.f;
    const float4* ap0 = (const float4*)(att0 + base);
    const float4* ap1 = att1 ? (const float4*)(att1 + base) : nullptr;
    const float4* ap2 = att2 ? (const float4*)(att2 + base) : nullptr;
#pragma unroll
    for (int q = 0; q < 4; q++) {
        float4 av = ap0[q];
        s0 += hv[q*4]*av.x + hv[q*4+1]*av.y + hv[q*4+2]*av.z + hv[q*4+3]*av.w;
        if (ap1) {
            float4 bv = ap1[q];
            s1 += hv[q*4]*bv.x + hv[q*4+1]*bv.y + hv[q*4+2]*bv.z + hv[q*4+3]*bv.w;
        }
        if (ap2) {
            float4 cv = ap2[q];
            s2 += hv[q*4]*cv.x + hv[q*4+1]*cv.y + hv[q*4+2]*cv.z + hv[q*4+3]*cv.w;
        }
    }
#pragma unroll
    for (int d = 1; d <= 2; d <<= 1) {
        s0 += __shfl_xor_sync(0xffffffffu, s0, d);
        s1 += __shfl_xor_sync(0xffffffffu, s1, d);
        s2 += __shfl_xor_sync(0xffffffffu, s2, d);
    }
    if ((lane & 3) == 0) {
        int o = warp * HH + (lane >> 2);
        a0[o] = s0;
        if (a1) a1[o] = s1;
        if (a2) a2[o] = s2;
    }
}

// ---------------- edge pass 1: alpha + segment max + degree -----------------
__global__ void edge_alpha_max2(
        const int* __restrict__ s0p, const int* __restrict__ d0p,
        const int* __restrict__ s1p, const int* __restrict__ d1p,
        const float* __restrict__ ase, const float* __restrict__ ade,
        const float* __restrict__ aso, const float* __restrict__ ado,
        float* __restrict__ alpha, unsigned* __restrict__ amax,
        int* __restrict__ deg, int ne) {
    int i = blockIdx.x * blockDim.x + threadIdx.x;
    int half = ne * HH;
    if (i >= 2 * half) return;
    int m = i >= half;
    int li = m ? i - half : i;
    int e = li >> 3, h = li & 7;
    const int* sp = m ? s1p : s0p;
    const int* dp = m ? d1p : d0p;
    const float* as = m ? aso : ase;
    const float* ad = m ? ado : ade;
    int d = dp[e];
    float v = as[sp[e] * HH + h] + ad[d * HH + h];
    v = (v > 0.f) ? v : 0.2f * v;
    alpha[i] = v;
    atomicMax(&amax[m * NN * HH + d * HH + h], mapf(v));
    if (h == 0) atomicAdd(&deg[m * NN + d], 1);
}

// ---------------- edge pass 2: exp + segment sum ----------------------------
__global__ void edge_exp_sum2(
        const int* __restrict__ d0p, const int* __restrict__ d1p,
        float* __restrict__ alpha, const unsigned* __restrict__ amax,
        float* __restrict__ denom, int ne) {
    int i = blockIdx.x * blockDim.x + threadIdx.x;
    int half = ne * HH;
    if (i >= 2 * half) return;
    int m = i >= half;
    int li = m ? i - half : i;
    int e = li >> 3, h = li & 7;
    const int* dp = m ? d1p : d0p;
    int off = m * NN * HH + dp[e] * HH + h;
    float ex = expf(alpha[i] - unmapf(amax[off]));
    alpha[i] = ex;
    atomicAdd(&denom[off], ex);
}

// ---------------- scans -------------------------------------------------------
__global__ void scan1(const int* __restrict__ vin, int* __restrict__ outv,
                      int* __restrict__ bsum, int n) {
    __shared__ int sh[1024];
    int gid = blockIdx.x * 1024 + threadIdx.x;
    int v = (gid < n) ? vin[gid] : 0;
    sh[threadIdx.x] = v;
    __syncthreads();
    for (int off = 1; off < 1024; off <<= 1) {
        int t = (threadIdx.x >= off) ? sh[threadIdx.x - off] : 0;
        __syncthreads();
        sh[threadIdx.x] += t;
        __syncthreads();
    }
    if (gid < n) outv[gid] = sh[threadIdx.x] - v;
    if (threadIdx.x == 1023) bsum[blockIdx.x] = sh[1023];
}

__global__ void scan2(int* __restrict__ bsum, int nb) {
    __shared__ int sh[256];
    int v = (threadIdx.x < nb) ? bsum[threadIdx.x] : 0;
    sh[threadIdx.x] = v;
    __syncthreads();
    for (int off = 1; off < 256; off <<= 1) {
        int t = (threadIdx.x >= off) ? sh[threadIdx.x - off] : 0;
        __syncthreads();
        sh[threadIdx.x] += t;
        __syncthreads();
    }
    if (threadIdx.x < nb) bsum[threadIdx.x] = sh[threadIdx.x] - v;
}

__global__ void scan3(int* __restrict__ outv, const int* __restrict__ bsum,
                      int n) {
    int gid = blockIdx.x * 1024 + threadIdx.x;
    if (gid < n) outv[gid] += bsum[blockIdx.x];
}

__global__ void make_ind(const int* __restrict__ deg, int* __restrict__ ind,
                         int n) {
    int i = blockIdx.x * blockDim.x + threadIdx.x;
    if (i < n) ind[i] = (deg[i] > 0) ? 1 : 0;
}

__global__ void meta_k(const int* __restrict__ nzpos,
                       const int* __restrict__ deg, int* __restrict__ meta) {
    int nz0 = nzpos[NN];
    int nztot = nzpos[2 * NN - 1] + ((deg[2 * NN - 1] > 0) ? 1 : 0);
    int P0 = (nz0 + 127) & ~127;
    int nz1 = nztot - nz0;
    meta[0] = nz0;
    meta[1] = P0;
    meta[2] = P0 + nz1;
    meta[3] = NN - nz1;
}

// zero the pad rows [nz0, P0) of Agg
__global__ void zero_pad(const int* __restrict__ meta,
                         __nv_bfloat16* __restrict__ Agg) {
    int nz0 = meta[0], P0 = meta[1];
    long total = (long)(P0 - nz0) * DD;
    long base = (size_t)nz0 * DD;
    for (long t = (long)blockIdx.x * blockDim.x + threadIdx.x; t < total;
         t += (long)gridDim.x * blockDim.x)
        Agg[base + t] = __float2bfloat16(0.f);
}

__global__ void csr_fill(
        const int* __restrict__ s0p, const int* __restrict__ d0p,
        const int* __restrict__ s1p, const int* __restrict__ d1p,
        const int* __restrict__ startv, int* __restrict__ cur,
        int* __restrict__ eidx, int* __restrict__ esrc, int ne) {
    int i = blockIdx.x * blockDim.x + threadIdx.x;
    if (i >= 2 * ne) return;
    int m = i >= ne;
    int le = m ? i - ne : i;
    int d = m ? d1p[le] : d0p[le];
    int s = m ? s1p[le] : s0p[le];
    int dd = m * NN + d;
    int pos = startv[dd] + atomicAdd(&cur[dd], 1);
    eidx[pos] = i;
    esrc[pos] = s;
}

// ---------------- gather -> compacted Agg ------------------------------------
__global__ void gather_conv(
        const int* __restrict__ eidx, const int* __restrict__ esrc,
        const int* __restrict__ startv, const int* __restrict__ deg,
        const int* __restrict__ nzpos, const int* __restrict__ meta,
        const __nv_bfloat16* __restrict__ h0,
        const __nv_bfloat16* __restrict__ h1,
        const float* __restrict__ ebuf, const float* __restrict__ denom,
        __nv_bfloat16* __restrict__ Agg) {
    int gw = (blockIdx.x * blockDim.x + threadIdx.x) >> 5;
    int lane = threadIdx.x & 31;
    if (gw >= 2 * NN) return;
    int de = deg[gw];
    if (de == 0) return;
    int m = gw >= NN;
    const __nv_bfloat16* hs = m ? h1 : h0;
    int row = m ? (meta[1] + nzpos[gw] - meta[0]) : nzpos[gw];
    int st = startv[gw];
    int h = lane >> 2;
    float dinv = 1.0f / (denom[gw * HH + h] + 1e-16f);
    float acc[16];
#pragma unroll
    for (int q = 0; q < 16; q++) acc[q] = 0.f;

    for (int p = 0; p < de; p++) {
        int ge = eidx[st + p];
        int s  = esrc[st + p];
        float w = ebuf[ge * HH + h] * dinv;
        const uint4* hp = (const uint4*)(hs + (size_t)s * DD + lane * 16);
        uint4 qa = hp[0], qb = hp[1];
        __nv_bfloat162* pa = reinterpret_cast<__nv_bfloat162*>(&qa);
        __nv_bfloat162* pb = reinterpret_cast<__nv_bfloat162*>(&qb);
#pragma unroll
        for (int j = 0; j < 4; j++) {
            float2 f = __bfloat1622float2(pa[j]);
            acc[2 * j]     += f.x * w;
            acc[2 * j + 1] += f.y * w;
            float2 g = __bfloat1622float2(pb[j]);
            acc[8 + 2 * j]     += g.x * w;
            acc[8 + 2 * j + 1] += g.y * w;
        }
    }

    uint4 o1, o2;
#pragma unroll
    for (int j = 0; j < 8; j++) {
        float a = fmaxf(acc[2 * j], 0.f);
        float b = fmaxf(acc[2 * j + 1], 0.f);
        __nv_bfloat162 pk = __floats2bfloat162_rn(a, b);
        if (j < 4) (&o1.x)[j] = *reinterpret_cast<unsigned*>(&pk);
        else       (&o2.x)[j - 4] = *reinterpret_cast<unsigned*>(&pk);
    }
    uint4* dst = (uint4*)(Agg + (size_t)row * DD + lane * 16);
    dst[0] = o1;
    dst[1] = o2;
}

// ---------------- final: corrections + softmax + pool + linear ---------------
__global__ void final_kernel(const float* __restrict__ qsem,
                             const float* __restrict__ klb,
                             const float* __restrict__ linw,
                             const float* __restrict__ linb,
                             const int* __restrict__ meta,
                             float* __restrict__ out) {
    __shared__ float sh[DD];
    __shared__ float sv[2];
    int f = threadIdx.x;
    const float invN = 1.0f / (float)NN;
    float q = qsem[f];
    float tb = tanhf(klb[f]);
    float c0 = (float)(NN - meta[1]);   // zero rows excluded from bank0 gemm
    float c1 = (float)meta[3];          // NN - nz1
    float v0 = (g_ksum[f] + c0 * tb) * invN * q;
    float v1 = (g_ksum[DD + f] + c1 * tb) * invN * q;

    sh[f] = v0; __syncthreads();
    for (int s = 256; s > 0; s >>= 1) { if (f < s) sh[f] += sh[f + s]; __syncthreads(); }
    if (f == 0) sv[0] = sh[0];
    __syncthreads();
    sh[f] = v1; __syncthreads();
    for (int s = 256; s > 0; s >>= 1) { if (f < s) sh[f] += sh[f + s]; __syncthreads(); }
    if (f == 0) sv[1] = sh[0];
    __syncthreads();

    float s0 = sv[0], s1 = sv[1];
    float mx = fmaxf(s0, s1);
    float e0 = expf(s0 - mx), e1 = expf(s1 - mx);
    float sem0 = e0 / (e0 + e1), sem1 = e1 / (e0 + e1);

    float pooled = (sem0 * g_musum[f] + sem1 * g_musum[DD + f]) * invN;
    float w0 = pooled * linw[f * 2 + 0];
    float w1 = pooled * linw[f * 2 + 1];

    sh[f] = w0; __syncthreads();
    for (int s = 256; s > 0; s >>= 1) { if (f < s) sh[f] += sh[f + s]; __syncthreads(); }
    if (f == 0) out[0] = sh[0] + linb[0];
    __syncthreads();
    sh[f] = w1; __syncthreads();
    for (int s = 256; s > 0; s >>= 1) { if (f < s) sh[f] += sh[f + s]; __syncthreads(); }
    if (f == 0) out[1] = sh[0] + linb[1];
}

// ---------------- host launcher ---------------------------------------------
extern "C" void kernel_launch(void* const* d_in, const int* in_sizes, int n_in,
                              void* d_out, int out_size) {
    const float* x_o  = (const float*)d_in[0];
    const float* x_e  = (const float*)d_in[1];
    const int*   e2o  = (const int*)d_in[2];
    const int*   o2o  = (const int*)d_in[3];
    const float* powm = (const float*)d_in[4];
    const float* pob  = (const float*)d_in[5];
    const float* pewm = (const float*)d_in[6];
    const float* peb  = (const float*)d_in[7];
    const float* a_s_e2o = (const float*)d_in[8];
    const float* a_d_e2o = (const float*)d_in[9];
    const float* a_s_o2o = (const float*)d_in[10];
    const float* a_d_o2o = (const float*)d_in[11];
    const float* klw  = (const float*)d_in[12];
    const float* klb  = (const float*)d_in[13];
    const float* qsem = (const float*)d_in[14];
    const float* linw = (const float*)d_in[15];
    const float* linb = (const float*)d_in[16];
    float* out = (float*)d_out;

    void* p;
    float *a_se, *a_de, *a_so, *a_do, *denom, *ebuf, *ksum, *musum;
    __nv_bfloat16 *hb_o, *hb_e, *Ab, *Agg, *Wb;
    unsigned* amax;
    int *deg, *cur, *startv, *ind, *nzpos, *bsum, *bsum2, *meta, *eidx, *esrc;
    cudaGetSymbolAddress(&p, g_hb_o); hb_o = (__nv_bfloat16*)p;
    cudaGetSymbolAddress(&p, g_hb_e); hb_e = (__nv_bfloat16*)p;
    cudaGetSymbolAddress(&p, g_Ab);   Ab   = (__nv_bfloat16*)p;
    cudaGetSymbolAddress(&p, g_Agg);  Agg  = (__nv_bfloat16*)p;
    cudaGetSymbolAddress(&p, g_Wb);   Wb   = (__nv_bfloat16*)p;
    cudaGetSymbolAddress(&p, g_a_se); a_se = (float*)p;
    cudaGetSymbolAddress(&p, g_a_de); a_de = (float*)p;
    cudaGetSymbolAddress(&p, g_a_so); a_so = (float*)p;
    cudaGetSymbolAddress(&p, g_a_do); a_do = (float*)p;
    cudaGetSymbolAddress(&p, g_amax); amax = (unsigned*)p;
    cudaGetSymbolAddress(&p, g_denom); denom = (float*)p;
    cudaGetSymbolAddress(&p, g_ebuf); ebuf = (float*)p;
    cudaGetSymbolAddress(&p, g_deg);  deg  = (int*)p;
    cudaGetSymbolAddress(&p, g_cur);  cur  = (int*)p;
    cudaGetSymbolAddress(&p, g_startArr); startv = (int*)p;
    cudaGetSymbolAddress(&p, g_ind);  ind  = (int*)p;
    cudaGetSymbolAddress(&p, g_nzpos); nzpos = (int*)p;
    cudaGetSymbolAddress(&p, g_bsum); bsum = (int*)p;
    cudaGetSymbolAddress(&p, g_bsum2); bsum2 = (int*)p;
    cudaGetSymbolAddress(&p, g_meta); meta = (int*)p;
    cudaGetSymbolAddress(&p, g_eidx); eidx = (int*)p;
    cudaGetSymbolAddress(&p, g_esrc); esrc = (int*)p;
    cudaGetSymbolAddress(&p, g_ksum); ksum = (float*)p;
    cudaGetSymbolAddress(&p, g_musum); musum = (float*)p;

    const long ND = (long)NN * DD;
    dim3 tcgrid(DD / GBN, (NN + GBM - 1) / GBM);        // (4, 782)
    dim3 tcgrid2(DD / GBN, (2 * NN + GBM - 1) / GBM);   // worst case (4, 1563)
    const int NTOT = 2 * NN;
    const int SCAN_BLOCKS = (NTOT + 1023) / 1024;

    // ---- GEMM 1 as launch #4 (ncu capture point) ----
    conv_bf<<<256, 256>>>(powm, Wb, DD * DD);
    conv_bf<<<2048, 256>>>(x_o, Ab, ND);
    zero_buf<<<4, 256>>>(ksum, 2 * DD);
    gemm_bf<0><<<tcgrid, 256>>>(Ab, Wb, pob, hb_o, NN, nullptr, nullptr);

    zero_buf<<<4, 256>>>(musum, 2 * DD);

    // ---- GEMM 2 ----
    conv_bf<<<256, 256>>>(pewm, Wb, DD * DD);
    conv_bf<<<2048, 256>>>(x_e, Ab, ND);
    gemm_bf<0><<<tcgrid, 256>>>(Ab, Wb, peb, hb_e, NN, nullptr, nullptr);

    int ah_blocks = (NN * 32 + 255) / 256;
    int e2_blocks = (2 * EE * HH + 255) / 256;
    int ef_blocks = (2 * EE + 255) / 256;
    int ie_blocks = (2 * NN * HH + 255) / 256;
    int gw_blocks = (2 * NN * 32 + 255) / 256;

    // ---- attention dots ----
    compute_ah3<<<ah_blocks, 256>>>(hb_o, a_d_e2o, a_de, a_s_o2o, a_so, a_d_o2o, a_do, NN);
    compute_ah3<<<ah_blocks, 256>>>(hb_e, a_s_e2o, a_se, nullptr, nullptr, nullptr, nullptr, NN);

    // ---- edge passes ----
    init_edge_state2<<<ie_blocks, 256>>>(amax, denom, deg, cur, 2 * NN * HH);
    edge_alpha_max2<<<e2_blocks, 256>>>(e2o, e2o + EE, o2o, o2o + EE,
                                        a_se, a_de, a_so, a_do, ebuf, amax, deg, EE);
    edge_exp_sum2<<<e2_blocks, 256>>>(e2o + EE, o2o + EE, ebuf, amax, denom, EE);

    // ---- CSR scan + nonzero-compaction scan ----
    scan1<<<SCAN_BLOCKS, 1024>>>(deg, startv, bsum, NTOT);
    scan2<<<1, 256>>>(bsum, SCAN_BLOCKS);
    scan3<<<SCAN_BLOCKS, 1024>>>(startv, bsum, NTOT);
    make_ind<<<(NTOT + 255) / 256, 256>>>(deg, ind, NTOT);
    scan1<<<SCAN_BLOCKS, 1024>>>(ind, nzpos, bsum2, NTOT);
    scan2<<<1, 256>>>(bsum2, SCAN_BLOCKS);
    scan3<<<SCAN_BLOCKS, 1024>>>(nzpos, bsum2, NTOT);
    meta_k<<<1, 1>>>(nzpos, deg, meta);
    csr_fill<<<ef_blocks, 256>>>(e2o, e2o + EE, o2o, o2o + EE,
                                 startv, cur, eidx, esrc, EE);
    zero_pad<<<128, 256>>>(meta, Agg);

    // ---- gather -> compacted Agg ----
    gather_conv<<<gw_blocks, 256>>>(eidx, esrc, startv, deg, nzpos, meta,
                                    hb_e, hb_o, ebuf, denom, Agg);

    // ---- semantic attention on compacted rows ----
    conv_bf<<<256, 256>>>(klw, Wb, DD * DD);
    mu_bf2<<<256, 512>>>(Agg, musum, meta);
    gemm_bf<1><<<tcgrid2, 256>>>(Agg, Wb, klb, nullptr, 2 * NN, ksum, meta);

    // ---- corrections + softmax + pool + linear ----
    final_kernel<<<1, 512>>>(qsem, klb, linw, linb, meta, out);
}